// round 14
// baseline (speedup 1.0000x reference)
#include <cuda_runtime.h>
#include <cuda_bf16.h>
#include <math.h>
#include <stdint.h>

#define T 2048
#define D 1024
#define NH 16
#define HD 64
#define NE 8
#define FF 2048

typedef __nv_bfloat16 bf16;

// ---------------- fp32 scratch ----------------
__device__ float g_q[T*D];
__device__ float g_k[T*D];
__device__ float g_v[T*D];
__device__ float g_hs1[T*D];
__device__ float g_xln2[T*D];
__device__ float g_ypart[T*2*D];
__device__ float g_probs[T*NE];
__device__ float g_lse[T];
__device__ float g_gatew[T*2];
__device__ int   g_topk[T*2];
__device__ int   g_ecnt[NE];
__device__ int   g_eoff[NE];
__device__ int   g_elist[NE*T];
// ---------------- bf16 hi/lo operand arrays ----------------
__device__ bf16 g_xlnh[T*D],  g_xlnl[T*D];
__device__ bf16 g_xln2h[T*D], g_xln2l[T*D];
__device__ bf16 g_attnh[T*D], g_attnl[T*D];
__device__ bf16 g_qh[T*D], g_ql[T*D], g_kh[T*D], g_kl[T*D];
__device__ bf16 g_vTh[D*T], g_vTl[D*T];
__device__ bf16 g_hh[(2*T+128)*FF], g_hl[(2*T+128)*FF];

// ---------------- helpers ----------------
__device__ __forceinline__ uint32_t smem_u32(const void* p) {
    uint32_t a;
    asm("{ .reg .u64 t; cvta.to.shared.u64 t, %1; cvt.u32.u64 %0, t; }" : "=r"(a) : "l"(p));
    return a;
}
__device__ __forceinline__ void ldm_x4(uint32_t* r, uint32_t addr) {
    asm volatile("ldmatrix.sync.aligned.m8n8.x4.shared.b16 {%0,%1,%2,%3}, [%4];"
        : "=r"(r[0]), "=r"(r[1]), "=r"(r[2]), "=r"(r[3]) : "r"(addr));
}
__device__ __forceinline__ void ldm_x4_trans(uint32_t* r, uint32_t addr) {
    asm volatile("ldmatrix.sync.aligned.m8n8.x4.trans.shared.b16 {%0,%1,%2,%3}, [%4];"
        : "=r"(r[0]), "=r"(r[1]), "=r"(r[2]), "=r"(r[3]) : "r"(addr));
}
__device__ __forceinline__ void mma_bf16(float* c, const uint32_t* a, uint32_t b0, uint32_t b1) {
    asm volatile(
        "mma.sync.aligned.m16n8k16.row.col.f32.bf16.bf16.f32 "
        "{%0,%1,%2,%3}, {%4,%5,%6,%7}, {%8,%9}, {%0,%1,%2,%3};"
        : "+f"(c[0]), "+f"(c[1]), "+f"(c[2]), "+f"(c[3])
        : "r"(a[0]), "r"(a[1]), "r"(a[2]), "r"(a[3]), "r"(b0), "r"(b1));
}
__device__ __forceinline__ uint32_t pack_bf16(float a, float b) {
    __nv_bfloat162 t;
    t.x = __float2bfloat16(a); t.y = __float2bfloat16(b);
    return *(uint32_t*)&t;
}
__device__ __forceinline__ void split_store(bf16* ph, bf16* pl, size_t idx, float v0, float v1) {
    __nv_bfloat162 h, l;
    h.x = __float2bfloat16(v0); h.y = __float2bfloat16(v1);
    l.x = __float2bfloat16(v0 - __bfloat162float(h.x));
    l.y = __float2bfloat16(v1 - __bfloat162float(h.y));
    *(__nv_bfloat162*)&ph[idx] = h;
    *(__nv_bfloat162*)&pl[idx] = l;
}
__device__ __forceinline__ void cvt_split_u2(float4 b, uint2& hv, uint2& lv) {
    __nv_bfloat162 h0, h1, l0, l1;
    h0.x = __float2bfloat16(b.x); h0.y = __float2bfloat16(b.y);
    h1.x = __float2bfloat16(b.z); h1.y = __float2bfloat16(b.w);
    l0.x = __float2bfloat16(b.x - __bfloat162float(h0.x));
    l0.y = __float2bfloat16(b.y - __bfloat162float(h0.y));
    l1.x = __float2bfloat16(b.z - __bfloat162float(h1.x));
    l1.y = __float2bfloat16(b.w - __bfloat162float(h1.y));
    hv.x = *(uint32_t*)&h0; hv.y = *(uint32_t*)&h1;
    lv.x = *(uint32_t*)&l0; lv.y = *(uint32_t*)&l1;
}
#define CP_ASYNC16(sa, gp) \
    asm volatile("cp.async.cg.shared.global [%0], [%1], 16;" :: "r"(sa), "l"(gp))
#define CP_COMMIT() asm volatile("cp.async.commit_group;" ::: "memory")
#define CP_WAIT0() asm volatile("cp.async.wait_group 0;" ::: "memory")

// ---------------- transpose + bf16 split (V only) ----------------
__global__ __launch_bounds__(256) void transpose_split(const float* __restrict__ in,
                                                       bf16* __restrict__ oh,
                                                       bf16* __restrict__ ol,
                                                       int R, int C) {
    __shared__ float tile[32][33];
    int c0 = blockIdx.x * 32, r0 = blockIdx.y * 32;
    int tx = threadIdx.x & 31, ty = threadIdx.x >> 5;
    for (int i = ty; i < 32; i += 8)
        tile[i][tx] = in[(size_t)(r0 + i) * C + c0 + tx];
    __syncthreads();
    for (int i = ty; i < 32; i += 8) {
        float v = tile[tx][i];
        bf16 h = __float2bfloat16(v);
        oh[(size_t)(c0 + i) * R + r0 + tx] = h;
        ol[(size_t)(c0 + i) * R + r0 + tx] = __float2bfloat16(v - __bfloat162float(h));
    }
}

// ---------------- bf16x3 double-buffered tensor-core GEMM (cp.async A staging) ----------------
// mode 0: C=A@B   1: +res   4: A=compact g_hh rows, weighted scatter to g_ypart
#define STRIDE 40
#define BSTRIDE 136
#define ABUF 10240
#define BBUF 8704
#define GEMM_SMEM (4*ABUF + 4*BBUF)
__global__ __launch_bounds__(256, 1) void mma_gemm(const bf16* __restrict__ Ah_,
                                                   const bf16* __restrict__ Al_,
                                                   const float* __restrict__ B,
                                                   float* __restrict__ C,
                                                   const float* __restrict__ res,
                                                   int N, int K, int mode) {
    extern __shared__ char dyn[];
    uint32_t aAh = smem_u32(dyn);
    uint32_t aAl = aAh + 2 * ABUF;
    uint32_t aBh = aAh + 4 * ABUF;
    uint32_t aBl = aBh + 2 * BBUF;
    bf16* sBh = (bf16*)(dyn + 4 * ABUF);
    bf16* sBl = (bf16*)(dyn + 4 * ABUF + 2 * BBUF);
    __shared__ float swgt[128];
    __shared__ int sdst[128];

    int tid = threadIdx.x, wid = tid >> 5, lane = tid & 31;
    int e = blockIdx.z;
    int cnt = 0, goff = 0;
    int row0 = blockIdx.y * 128, col0 = blockIdx.x * 128;
    int K2 = K >> 1;
    const uint32_t* Ah = (const uint32_t*)Ah_;
    const uint32_t* Al = (const uint32_t*)Al_;
    if (mode == 4) {
        cnt = g_ecnt[e]; goff = g_eoff[e];
        if (row0 >= cnt) return;
        if (tid < 128) {
            int slot = row0 + tid;
            if (slot < cnt) {
                int p = g_elist[e * T + slot];
                int tt = p >> 1, ks = p & 1;
                swgt[tid] = g_gatew[tt * 2 + ks];
                sdst[tid] = tt * 2 + ks;
            } else { swgt[tid] = 0.f; sdst[tid] = -1; }
        }
        B += (size_t)e * (size_t)K * (size_t)N;
        __syncthreads();
    }

    int wr = wid & 3, wc = wid >> 2;
    float acc[2][8][4] = {};

    int nchunks = K >> 5;
    float4 bR[4];

    // async A staging: 2 fragments x (hi,lo) = 4 x 16B per thread per chunk
    auto issueA = [&](int chunk, int buf) {
        int kc0 = chunk * 16;
        uint32_t ao = (uint32_t)(buf * ABUF);
        #pragma unroll
        for (int f = 0; f < 2; f++) {
            int fi = tid + f * 256; int r = fi >> 2, c4 = fi & 3;
            size_t arow = (mode == 4) ? (size_t)(goff + row0 + r) : (size_t)(row0 + r);
            uint32_t so = (uint32_t)(r * (STRIDE / 2) + c4 * 4) * 4;
            CP_ASYNC16(aAh + ao + so, Ah + arow * K2 + kc0 + c4 * 4);
            CP_ASYNC16(aAl + ao + so, Al + arow * K2 + kc0 + c4 * 4);
        }
        CP_COMMIT();
    };
    auto loadB = [&](int chunk) {
        int kr0 = chunk * 32;
        #pragma unroll
        for (int f = 0; f < 4; f++) {
            int fi = tid + f * 256; int r = fi >> 5, c = (fi & 31) * 4;
            bR[f] = *(const float4*)&B[(size_t)(kr0 + r) * N + col0 + c];
        }
    };
    auto storeB = [&](int buf) {
        int bo = buf * (BBUF / 2);
        #pragma unroll
        for (int f = 0; f < 4; f++) {
            int fi = tid + f * 256; int r = fi >> 5, c = (fi & 31) * 4;
            int si = bo + r * BSTRIDE + c;
            uint2 hv, lv;
            cvt_split_u2(bR[f], hv, lv);
            *(uint2*)&sBh[si] = hv;
            *(uint2*)&sBl[si] = lv;
        }
    };

    int lrow = lane & 15;
    int lcol8 = (lane >> 4) << 3;
    int tb_k = (lane & 7) + ((lane >> 4) << 3);
    int tb_n = ((lane >> 3) & 1) << 3;

    issueA(0, 0);
    loadB(0);
    storeB(0);
    CP_WAIT0();
    __syncthreads();

    for (int i = 0; i < nchunks; i++) {
        int b = i & 1;
        if (i + 1 < nchunks) { issueA(i + 1, b ^ 1); loadB(i + 1); }
        uint32_t Aoff = (uint32_t)(b * ABUF);
        uint32_t Boff = (uint32_t)(b * BBUF);
        #pragma unroll
        for (int ks = 0; ks < 2; ks++) {
            int k0 = ks * 16;
            uint32_t ah[2][4], al[2][4];
            #pragma unroll
            for (int im = 0; im < 2; im++) {
                uint32_t off = (uint32_t)((wr * 32 + im * 16 + lrow) * STRIDE + k0 + lcol8) * 2 + Aoff;
                ldm_x4(ah[im], aAh + off);
                ldm_x4(al[im], aAl + off);
            }
            #pragma unroll
            for (int np = 0; np < 4; np++) {
                uint32_t off = (uint32_t)((k0 + tb_k) * BSTRIDE + wc * 64 + np * 16 + tb_n) * 2 + Boff;
                uint32_t bh[4], bl[4];
                ldm_x4_trans(bh, aBh + off);
                ldm_x4_trans(bl, aBl + off);
                #pragma unroll
                for (int im = 0; im < 2; im++) {
                    mma_bf16(acc[im][np * 2],     ah[im], bh[0], bh[2]);
                    mma_bf16(acc[im][np * 2],     ah[im], bl[0], bl[2]);
                    mma_bf16(acc[im][np * 2],     al[im], bh[0], bh[2]);
                    mma_bf16(acc[im][np * 2 + 1], ah[im], bh[1], bh[3]);
                    mma_bf16(acc[im][np * 2 + 1], ah[im], bl[1], bl[3]);
                    mma_bf16(acc[im][np * 2 + 1], al[im], bh[1], bh[3]);
                }
            }
        }
        if (i + 1 < nchunks) storeB(b ^ 1);
        CP_WAIT0();
        __syncthreads();
    }

    // ---------------- epilogue ----------------
    #pragma unroll
    for (int im = 0; im < 2; im++) {
        #pragma unroll
        for (int nt = 0; nt < 8; nt++) {
            int col = wc * 64 + nt * 8 + (lane & 3) * 2;
            int n = col0 + col;
            #pragma unroll
            for (int half = 0; half < 2; half++) {
                int slot = wr * 32 + im * 16 + (lane >> 2) + half * 8;
                float v0 = acc[im][nt][half * 2], v1 = acc[im][nt][half * 2 + 1];
                if (mode == 0) {
                    *(float2*)&C[(size_t)(row0 + slot) * N + n] = make_float2(v0, v1);
                } else if (mode == 1) {
                    size_t di = (size_t)(row0 + slot) * N + n;
                    float2 rr = *(const float2*)&res[di];
                    *(float2*)&C[di] = make_float2(v0 + rr.x, v1 + rr.y);
                } else {
                    if (row0 + slot < cnt && sdst[slot] >= 0) {
                        float w = swgt[slot];
                        *(float2*)&g_ypart[(size_t)sdst[slot] * D + n] = make_float2(w * v0, w * v1);
                    }
                }
            }
        }
    }
}

// ---------------- fused MoE gate+up GEMM: h = silu(x@Wg) * (x@Wu) ----------------
#define BS2 72
#define GBUF 4608
#define GU_SMEM (4*ABUF + 8*GBUF)
__global__ __launch_bounds__(256, 1) void moe_gateup(const bf16* __restrict__ Ah_,
                                                     const bf16* __restrict__ Al_,
                                                     const float* __restrict__ Wg,
                                                     const float* __restrict__ Wu) {
    extern __shared__ char dyn[];
    uint32_t aAh = smem_u32(dyn);
    uint32_t aAl = aAh + 2 * ABUF;
    uint32_t aGh = aAh + 4 * ABUF;
    uint32_t aGl = aGh + 2 * GBUF;
    uint32_t aUh = aGh + 4 * GBUF;
    uint32_t aUl = aGh + 6 * GBUF;
    bf16* sGh = (bf16*)(dyn + 4 * ABUF);
    bf16* sGl = (bf16*)(dyn + 4 * ABUF + 2 * GBUF);
    bf16* sUh = (bf16*)(dyn + 4 * ABUF + 4 * GBUF);
    bf16* sUl = (bf16*)(dyn + 4 * ABUF + 6 * GBUF);
    __shared__ int toks[128];

    int tid = threadIdx.x, wid = tid >> 5, lane = tid & 31;
    int e = blockIdx.z;
    int cnt = g_ecnt[e], goff = g_eoff[e];
    int row0 = blockIdx.y * 128, col0 = blockIdx.x * 64;
    if (row0 >= cnt) return;
    Wg += (size_t)e * D * FF;
    Wu += (size_t)e * D * FF;
    if (tid < 128) {
        int slot = row0 + tid;
        toks[tid] = (slot < cnt) ? (g_elist[e * T + slot] >> 1) : 0;
    }
    __syncthreads();

    const uint32_t* Ah = (const uint32_t*)Ah_;
    const uint32_t* Al = (const uint32_t*)Al_;
    int wr = wid & 3, wc = wid >> 2;
    float aG[2][4][4] = {}, aU[2][4][4] = {};

    float4 gR[2], uR[2];
    auto issueA = [&](int chunk, int buf) {
        int kc0 = chunk * 16;
        uint32_t ao = (uint32_t)(buf * ABUF);
        #pragma unroll
        for (int f = 0; f < 2; f++) {
            int fi = tid + f * 256; int r = fi >> 2, c4 = fi & 3;
            size_t arow = (size_t)toks[r];
            uint32_t so = (uint32_t)(r * (STRIDE / 2) + c4 * 4) * 4;
            CP_ASYNC16(aAh + ao + so, Ah + arow * (D / 2) + kc0 + c4 * 4);
            CP_ASYNC16(aAl + ao + so, Al + arow * (D / 2) + kc0 + c4 * 4);
        }
        CP_COMMIT();
    };
    auto loadB = [&](int chunk) {
        int kr0 = chunk * 32;
        #pragma unroll
        for (int f = 0; f < 2; f++) {
            int fi = tid + f * 256; int r = fi >> 4, c = (fi & 15) * 4;
            gR[f] = *(const float4*)&Wg[(size_t)(kr0 + r) * FF + col0 + c];
            uR[f] = *(const float4*)&Wu[(size_t)(kr0 + r) * FF + col0 + c];
        }
    };
    auto storeB = [&](int buf) {
        int bo = buf * (GBUF / 2);
        #pragma unroll
        for (int f = 0; f < 2; f++) {
            int fi = tid + f * 256; int r = fi >> 4, c = (fi & 15) * 4;
            int si = bo + r * BS2 + c;
            uint2 hv, lv;
            cvt_split_u2(gR[f], hv, lv);
            *(uint2*)&sGh[si] = hv; *(uint2*)&sGl[si] = lv;
            cvt_split_u2(uR[f], hv, lv);
            *(uint2*)&sUh[si] = hv; *(uint2*)&sUl[si] = lv;
        }
    };

    int lrow = lane & 15;
    int lcol8 = (lane >> 4) << 3;
    int tb_k = (lane & 7) + ((lane >> 4) << 3);
    int tb_n = ((lane >> 3) & 1) << 3;

    issueA(0, 0);
    loadB(0);
    storeB(0);
    CP_WAIT0();
    __syncthreads();

    int nchunks = D >> 5;
    for (int i = 0; i < nchunks; i++) {
        int b = i & 1;
        if (i + 1 < nchunks) { issueA(i + 1, b ^ 1); loadB(i + 1); }
        uint32_t Aoff = (uint32_t)(b * ABUF);
        uint32_t Boff = (uint32_t)(b * GBUF);
        #pragma unroll
        for (int ks = 0; ks < 2; ks++) {
            int k0 = ks * 16;
            uint32_t ah[2][4], al[2][4];
            #pragma unroll
            for (int im = 0; im < 2; im++) {
                uint32_t off = (uint32_t)((wr * 32 + im * 16 + lrow) * STRIDE + k0 + lcol8) * 2 + Aoff;
                ldm_x4(ah[im], aAh + off);
                ldm_x4(al[im], aAl + off);
            }
            #pragma unroll
            for (int np = 0; np < 2; np++) {
                uint32_t off = (uint32_t)((k0 + tb_k) * BS2 + wc * 32 + np * 16 + tb_n) * 2 + Boff;
                uint32_t bh[4], bl[4];
                ldm_x4_trans(bh, aGh + off);
                ldm_x4_trans(bl, aGl + off);
                #pragma unroll
                for (int im = 0; im < 2; im++) {
                    mma_bf16(aG[im][np * 2],     ah[im], bh[0], bh[2]);
                    mma_bf16(aG[im][np * 2],     ah[im], bl[0], bl[2]);
                    mma_bf16(aG[im][np * 2],     al[im], bh[0], bh[2]);
                    mma_bf16(aG[im][np * 2 + 1], ah[im], bh[1], bh[3]);
                    mma_bf16(aG[im][np * 2 + 1], ah[im], bl[1], bl[3]);
                    mma_bf16(aG[im][np * 2 + 1], al[im], bh[1], bh[3]);
                }
                ldm_x4_trans(bh, aUh + off);
                ldm_x4_trans(bl, aUl + off);
                #pragma unroll
                for (int im = 0; im < 2; im++) {
                    mma_bf16(aU[im][np * 2],     ah[im], bh[0], bh[2]);
                    mma_bf16(aU[im][np * 2],     ah[im], bl[0], bl[2]);
                    mma_bf16(aU[im][np * 2],     al[im], bh[0], bh[2]);
                    mma_bf16(aU[im][np * 2 + 1], ah[im], bh[1], bh[3]);
                    mma_bf16(aU[im][np * 2 + 1], ah[im], bl[1], bl[3]);
                    mma_bf16(aU[im][np * 2 + 1], al[im], bh[1], bh[3]);
                }
            }
        }
        if (i + 1 < nchunks) storeB(b ^ 1);
        CP_WAIT0();
        __syncthreads();
    }

    #pragma unroll
    for (int im = 0; im < 2; im++) {
        #pragma unroll
        for (int nt = 0; nt < 4; nt++) {
            int n = col0 + wc * 32 + nt * 8 + (lane & 3) * 2;
            #pragma unroll
            for (int half = 0; half < 2; half++) {
                int slot = wr * 32 + im * 16 + (lane >> 2) + half * 8;
                if (row0 + slot < cnt) {
                    float gg0 = aG[im][nt][half * 2], gg1 = aG[im][nt][half * 2 + 1];
                    float u0 = aU[im][nt][half * 2], u1 = aU[im][nt][half * 2 + 1];
                    float h0 = u0 * (gg0 / (1.f + __expf(-gg0)));
                    float h1 = u1 * (gg1 / (1.f + __expf(-gg1)));
                    split_store(g_hh, g_hl, (size_t)(goff + row0 + slot) * FF + n, h0, h1);
                }
            }
        }
    }
}

// ---------------- LayerNorm (+ bf16 hi/lo split out) ----------------
__global__ __launch_bounds__(256) void ln_kernel(const float* __restrict__ x,
                                                 const float* __restrict__ w,
                                                 const float* __restrict__ b,
                                                 float* __restrict__ out,
                                                 bf16* __restrict__ oh,
                                                 bf16* __restrict__ ol) {
    int t = blockIdx.x;
    const float* row = x + (size_t)t * D;
    __shared__ float sh[256];
    int tid = threadIdx.x;
    float s = 0.f;
    for (int i = tid; i < D; i += 256) s += row[i];
    sh[tid] = s; __syncthreads();
    for (int o = 128; o; o >>= 1) { if (tid < o) sh[tid] += sh[tid + o]; __syncthreads(); }
    float mean = sh[0] / D;
    __syncthreads();
    float v = 0.f;
    for (int i = tid; i < D; i += 256) { float dd = row[i] - mean; v += dd * dd; }
    sh[tid] = v; __syncthreads();
    for (int o = 128; o; o >>= 1) { if (tid < o) sh[tid] += sh[tid + o]; __syncthreads(); }
    float rstd = rsqrtf(sh[0] / D + 1e-5f);
    for (int i2 = tid; i2 < D / 2; i2 += 256) {
        int i = i2 * 2;
        float y0 = (row[i] - mean) * rstd * w[i] + b[i];
        float y1 = (row[i + 1] - mean) * rstd * w[i + 1] + b[i + 1];
        size_t di = (size_t)t * D + i;
        if (out) *(float2*)&out[di] = make_float2(y0, y1);
        split_store(oh, ol, di, y0, y1);
    }
}

// ---------------- RoPE + bf16 split of q, k ----------------
__global__ __launch_bounds__(256) void rope_split_kernel() {
    int t = blockIdx.x;
    for (int p = threadIdx.x; p < D / 2; p += 256) {
        int head = p >> 5;
        int i = p & 31;
        int i1 = t * D + head * HD + i;
        int i2 = i1 + 32;
        float inv = expf(-(2.0f * i / HD) * 9.210340371976184f);
        float fr = (float)t * inv;
        float c = cosf(fr), s = sinf(fr);
        float q1 = g_q[i1], q2 = g_q[i2];
        float k1 = g_k[i1], k2 = g_k[i2];
        float qa = q1 * c - q2 * s, qb = q2 * c + q1 * s;
        float ka = k1 * c - k2 * s, kb = k2 * c + k1 * s;
        bf16 h;
        h = __float2bfloat16(qa); g_qh[i1] = h; g_ql[i1] = __float2bfloat16(qa - __bfloat162float(h));
        h = __float2bfloat16(qb); g_qh[i2] = h; g_ql[i2] = __float2bfloat16(qb - __bfloat162float(h));
        h = __float2bfloat16(ka); g_kh[i1] = h; g_kl[i1] = __float2bfloat16(ka - __bfloat162float(h));
        h = __float2bfloat16(kb); g_kh[i2] = h; g_kl[i2] = __float2bfloat16(kb - __bfloat162float(h));
    }
}

// ---------------- tensor-core flash attention: cp.async double-buffered K/V ----------------
#define AS 72
#define ABUFSZ 36864
#define ATTN_SMEM (2 * ABUFSZ)
__global__ __launch_bounds__(128) void attn_mma_kernel() {
    extern __shared__ bf16 asm_[];
    int qt = blockIdx.x, h = blockIdx.y;
    int tid = threadIdx.x, w = tid >> 5, lane = tid & 31;
    int lrow = lane & 15, lcol8 = (lane >> 4) << 3;
    uint32_t aBase = smem_u32(asm_);
    uint32_t* sKBh32 = (uint32_t*)asm_;
    uint32_t* sKBl32 = (uint32_t*)((char*)asm_ + 9216);
    const uint32_t* qh32 = (const uint32_t*)g_qh;
    const uint32_t* ql32 = (const uint32_t*)g_ql;
    const uint32_t* kh32 = (const uint32_t*)g_kh;
    const uint32_t* kl32 = (const uint32_t*)g_kl;
    const uint32_t* vth32 = (const uint32_t*)g_vTh;
    const uint32_t* vtl32 = (const uint32_t*)g_vTl;

    for (int i = tid; i < 64 * 32; i += 128) {
        int r = i >> 5, c = i & 31;
        sKBh32[r * (AS / 2) + c] = qh32[(size_t)(qt * 64 + r) * (D / 2) + h * 32 + c];
        sKBl32[r * (AS / 2) + c] = ql32[(size_t)(qt * 64 + r) * (D / 2) + h * 32 + c];
    }
    __syncthreads();
    uint32_t qah[4][4], qal[4][4];
    #pragma unroll
    for (int kc = 0; kc < 4; kc++) {
        uint32_t off = (uint32_t)((w * 16 + lrow) * AS + kc * 16 + lcol8) * 2;
        ldm_x4(qah[kc], aBase + off);
        ldm_x4(qal[kc], aBase + 9216 + off);
    }
    __syncthreads();

    auto issue_tile = [&](int kt, int b) {
        int kb = kt * 64;
        uint32_t base = aBase + (uint32_t)b * ABUFSZ;
        #pragma unroll
        for (int f = 0; f < 4; f++) {
            int j = tid + f * 128;
            int r = j >> 3, c4 = (j & 7) * 4;
            uint32_t so = (uint32_t)(r * (AS / 2) + c4) * 4;
            CP_ASYNC16(base + so,         kh32 + (size_t)(kb + r) * (D / 2) + h * 32 + c4);
            CP_ASYNC16(base + 9216 + so,  kl32 + (size_t)(kb + r) * (D / 2) + h * 32 + c4);
            CP_ASYNC16(base + 18432 + so, vth32 + (size_t)(h * 64 + r) * (T / 2) + (kb >> 1) + c4);
            CP_ASYNC16(base + 27648 + so, vtl32 + (size_t)(h * 64 + r) * (T / 2) + (kb >> 1) + c4);
        }
        CP_COMMIT();
    };

    float O[8][4] = {};
    float m_lo = -1e30f, m_hi = -1e30f, l_lo = 0.f, l_hi = 0.f;
    int row_lo = qt * 64 + w * 16 + (lane >> 2);
    int row_hi = row_lo + 8;
    int nkt = qt + 1;
    issue_tile(0, 0);
    for (int kt = 0; kt < nkt; kt++) {
        int b = kt & 1;
        CP_WAIT0();
        __syncthreads();
        if (kt + 1 < nkt) issue_tile(kt + 1, b ^ 1);
        uint32_t bb = aBase + (uint32_t)b * ABUFSZ;
        int kb = kt * 64;
        float S[8][4] = {};
        #pragma unroll
        for (int kc = 0; kc < 4; kc++) {
            #pragma unroll
            for (int jj = 0; jj < 4; jj++) {
                uint32_t off = (uint32_t)((jj * 16 + lrow) * AS + kc * 16 + lcol8) * 2;
                uint32_t bh[4], bl[4];
                ldm_x4(bh, bb + off);
                ldm_x4(bl, bb + 9216 + off);
                mma_bf16(S[2 * jj],     qah[kc], bh[0], bh[2]);
                mma_bf16(S[2 * jj],     qah[kc], bl[0], bl[2]);
                mma_bf16(S[2 * jj],     qal[kc], bh[0], bh[2]);
                mma_bf16(S[2 * jj + 1], qah[kc], bh[1], bh[3]);
                mma_bf16(S[2 * jj + 1], qah[kc], bl[1], bl[3]);
                mma_bf16(S[2 * jj + 1], qal[kc], bh[1], bh[3]);
            }
        }
        bool diag = (kt == qt);
        float mt_lo = -1e30f, mt_hi = -1e30f;
        #pragma unroll
        for (int j = 0; j < 8; j++) {
            int c0 = kb + j * 8 + ((lane & 3) << 1);
            float s0 = S[j][0] * 0.125f, s1 = S[j][1] * 0.125f;
            float s2 = S[j][2] * 0.125f, s3 = S[j][3] * 0.125f;
            if (diag) {
                if (c0 > row_lo) s0 = -1e30f;
                if (c0 + 1 > row_lo) s1 = -1e30f;
                if (c0 > row_hi) s2 = -1e30f;
                if (c0 + 1 > row_hi) s3 = -1e30f;
            }
            S[j][0] = s0; S[j][1] = s1; S[j][2] = s2; S[j][3] = s3;
            mt_lo = fmaxf(mt_lo, fmaxf(s0, s1));
            mt_hi = fmaxf(mt_hi, fmaxf(s2, s3));
        }
        mt_lo = fmaxf(mt_lo, __shfl_xor_sync(0xffffffff, mt_lo, 1));
        mt_lo = fmaxf(mt_lo, __shfl_xor_sync(0xffffffff, mt_lo, 2));
        mt_hi = fmaxf(mt_hi, __shfl_xor_sync(0xffffffff, mt_hi, 1));
        mt_hi = fmaxf(mt_hi, __shfl_xor_sync(0xffffffff, mt_hi, 2));
        float mn_lo = fmaxf(m_lo, mt_lo), mn_hi = fmaxf(m_hi, mt_hi);
        float co_lo = __expf(m_lo - mn_lo), co_hi = __expf(m_hi - mn_hi);
        l_lo *= co_lo; l_hi *= co_hi;
        #pragma unroll
        for (int j = 0; j < 8; j++) {
            O[j][0] *= co_lo; O[j][1] *= co_lo;
            O[j][2] *= co_hi; O[j][3] *= co_hi;
            S[j][0] = __expf(S[j][0] - mn_lo);
            S[j][1] = __expf(S[j][1] - mn_lo);
            S[j][2] = __expf(S[j][2] - mn_hi);
            S[j][3] = __expf(S[j][3] - mn_hi);
            l_lo += S[j][0] + S[j][1];
            l_hi += S[j][2] + S[j][3];
        }
        m_lo = mn_lo; m_hi = mn_hi;
        #pragma unroll
        for (int kc = 0; kc < 4; kc++) {
            uint32_t pah[4], pal[4];
            {
                float p0 = S[2 * kc][0], p1 = S[2 * kc][1], p2 = S[2 * kc][2], p3 = S[2 * kc][3];
                float q0 = S[2 * kc + 1][0], q1 = S[2 * kc + 1][1], q2 = S[2 * kc + 1][2], q3 = S[2 * kc + 1][3];
                pah[0] = pack_bf16(p0, p1); pah[1] = pack_bf16(p2, p3);
                pah[2] = pack_bf16(q0, q1); pah[3] = pack_bf16(q2, q3);
                __nv_bfloat162 t;
                t = *(__nv_bfloat162*)&pah[0];
                pal[0] = pack_bf16(p0 - __bfloat162float(t.x), p1 - __bfloat162float(t.y));
                t = *(__nv_bfloat162*)&pah[1];
                pal[1] = pack_bf16(p2 - __bfloat162float(t.x), p3 - __bfloat162float(t.y));
                t = *(__nv_bfloat162*)&pah[2];
                pal[2] = pack_bf16(q0 - __bfloat162float(t.x), q1 - __bfloat162float(t.y));
                t = *(__nv_bfloat162*)&pah[3];
                pal[3] = pack_bf16(q2 - __bfloat162float(t.x), q3 - __bfloat162float(t.y));
            }
            #pragma unroll
            for (int dd = 0; dd < 4; dd++) {
                uint32_t off = (uint32_t)((dd * 16 + lrow) * AS + kc * 16 + lcol8) * 2;
                uint32_t vh[4], vl[4];
                ldm_x4(vh, bb + 18432 + off);
                ldm_x4(vl, bb + 27648 + off);
                mma_bf16(O[2 * dd],     pah, vh[0], vh[2]);
                mma_bf16(O[2 * dd],     pah, vl[0], vl[2]);
                mma_bf16(O[2 * dd],     pal, vh[0], vh[2]);
                mma_bf16(O[2 * dd + 1], pah, vh[1], vh[3]);
                mma_bf16(O[2 * dd + 1], pah, vl[1], vl[3]);
                mma_bf16(O[2 * dd + 1], pal, vh[1], vh[3]);
            }
        }
    }
    l_lo += __shfl_xor_sync(0xffffffff, l_lo, 1);
    l_lo += __shfl_xor_sync(0xffffffff, l_lo, 2);
    l_hi += __shfl_xor_sync(0xffffffff, l_hi, 1);
    l_hi += __shfl_xor_sync(0xffffffff, l_hi, 2);
    float inv_lo = 1.f / l_lo, inv_hi = 1.f / l_hi;
    #pragma unroll
    for (int j = 0; j < 8; j++) {
        int col = h * 64 + j * 8 + ((lane & 3) << 1);
        split_store(g_attnh, g_attnl, (size_t)row_lo * D + col, O[j][0] * inv_lo, O[j][1] * inv_lo);
        split_store(g_attnh, g_attnl, (size_t)row_hi * D + col, O[j][2] * inv_hi, O[j][3] * inv_hi);
    }
}

// ---------------- router ----------------
__global__ __launch_bounds__(256) void zero_cnt_kernel() {
    if (threadIdx.x < NE) g_ecnt[threadIdx.x] = 0;
}

__global__ __launch_bounds__(256) void router_kernel(const float* __restrict__ wr) {
    int t = blockIdx.x;
    int tid = threadIdx.x, lane = tid & 31, w = tid >> 5;
    const float* x = g_xln2 + (size_t)t * D;
    float s = 0.f;
    for (int d = lane; d < D; d += 32) s += x[d] * wr[d * NE + w];
    #pragma unroll
    for (int o = 16; o; o >>= 1) s += __shfl_xor_sync(0xffffffff, s, o);
    __shared__ float lg[NE];
    if (lane == 0) lg[w] = s;
    __syncthreads();
    if (tid == 0) {
        float mx = -1e30f;
        #pragma unroll
        for (int e = 0; e < NE; e++) mx = fmaxf(mx, lg[e]);
        float ex[NE], sum = 0.f;
        #pragma unroll
        for (int e = 0; e < NE; e++) { ex[e] = expf(lg[e] - mx); sum += ex[e]; }
        g_lse[t] = mx + logf(sum);
        float pr[NE];
        #pragma unroll
        for (int e = 0; e < NE; e++) { pr[e] = ex[e] / sum; g_probs[t * NE + e] = pr[e]; }
        int e0 = 0; float b0 = pr[0];
        #pragma unroll
        for (int e = 1; e < NE; e++) if (pr[e] > b0) { b0 = pr[e]; e0 = e; }
        int e1 = -1; float b1 = -1.f;
        #pragma unroll
        for (int e = 0; e < NE; e++) if (e != e0 && pr[e] > b1) { b1 = pr[e]; e1 = e; }
        float ws = b0 + b1;
        g_gatew[t * 2 + 0] = b0 / ws;
        g_gatew[t * 2 + 1] = b1 / ws;
        g_topk[t * 2 + 0] = e0;
        g_topk[t * 2 + 1] = e1;
        int s0 = atomicAdd(&g_ecnt[e0], 1); g_elist[e0 * T + s0] = (t << 1) | 0;
        int s1 = atomicAdd(&g_ecnt[e1], 1); g_elist[e1 * T + s1] = (t << 1) | 1;
    }
}

__global__ void scan_kernel() {
    if (threadIdx.x == 0) {
        int o = 0;
        for (int e = 0; e < NE; e++) { g_eoff[e] = o; o += g_ecnt[e]; }
    }
}

// ---------------- final combine ----------------
__global__ __launch_bounds__(256) void combine_kernel(float* __restrict__ out) {
    int i = blockIdx.x * 256 + threadIdx.x;
    int t = i >> 10, d = i & 1023;
    out[i] = g_hs1[i] + g_ypart[(size_t)(t * 2) * D + d] + g_ypart[(size_t)(t * 2 + 1) * D + d];
}

// ---------------- aux losses ----------------
__global__ __launch_bounds__(256) void aux_kernel(float* __restrict__ out) {
    __shared__ float sh[256];
    __shared__ float totps[NE];
    __shared__ int totcnt[NE];
    __shared__ float zsave;
    int tid = threadIdx.x;
    if (tid < NE) totcnt[tid] = 0;
    float z = 0.f, ps[NE]; int cnt[NE];
    #pragma unroll
    for (int e = 0; e < NE; e++) { ps[e] = 0.f; cnt[e] = 0; }
    for (int t = tid; t < T; t += 256) {
        float l = g_lse[t]; z += l * l;
        #pragma unroll
        for (int e = 0; e < NE; e++) ps[e] += g_probs[t * NE + e];
        cnt[g_topk[t * 2]]++; cnt[g_topk[t * 2 + 1]]++;
    }
    sh[tid] = z; __syncthreads();
    for (int o = 128; o; o >>= 1) { if (tid < o) sh[tid] += sh[tid + o]; __syncthreads(); }
    if (tid == 0) zsave = sh[0];
    __syncthreads();
    for (int e = 0; e < NE; e++) {
        sh[tid] = ps[e]; __syncthreads();
        for (int o = 128; o; o >>= 1) { if (tid < o) sh[tid] += sh[tid + o]; __syncthreads(); }
        if (tid == 0) totps[e] = sh[0];
        __syncthreads();
        atomicAdd(&totcnt[e], cnt[e]);
    }
    __syncthreads();
    if (tid == 0) {
        float zl = 0.001f * zsave / T;
        float lb = 0.f;
        for (int e = 0; e < NE; e++) lb += ((float)totcnt[e] / T) * (totps[e] / T);
        out[T * D] = zl + 0.01f * lb;
    }
}

// ---------------- launch ----------------
extern "C" void kernel_launch(void* const* d_in, const int* in_sizes, int n_in,
                              void* d_out, int out_size) {
    const float* hs  = (const float*)d_in[0];
    const float* l1w = (const float*)d_in[3];
    const float* l1b = (const float*)d_in[4];
    const float* l2w = (const float*)d_in[5];
    const float* l2b = (const float*)d_in[6];
    const float* wq  = (const float*)d_in[7];
    const float* wk  = (const float*)d_in[8];
    const float* wv  = (const float*)d_in[9];
    const float* wo  = (const float*)d_in[10];
    const float* wr  = (const float*)d_in[11];
    const float* wg  = (const float*)d_in[12];
    const float* wu  = (const float*)d_in[13];
    const float* wd  = (const float*)d_in[14];
    float* out = (float*)d_out;

    float *q, *k, *v, *hs1, *xln2;
    bf16 *xlnh, *xlnl, *xln2h, *xln2l, *attnh, *attnl, *hh, *hl, *vTh, *vTl;
    cudaGetSymbolAddress((void**)&q,     g_q);
    cudaGetSymbolAddress((void**)&k,     g_k);
    cudaGetSymbolAddress((void**)&v,     g_v);
    cudaGetSymbolAddress((void**)&hs1,   g_hs1);
    cudaGetSymbolAddress((void**)&xln2,  g_xln2);
    cudaGetSymbolAddress((void**)&xlnh,  g_xlnh);
    cudaGetSymbolAddress((void**)&xlnl,  g_xlnl);
    cudaGetSymbolAddress((void**)&xln2h, g_xln2h);
    cudaGetSymbolAddress((void**)&xln2l, g_xln2l);
    cudaGetSymbolAddress((void**)&attnh, g_attnh);
    cudaGetSymbolAddress((void**)&attnl, g_attnl);
    cudaGetSymbolAddress((void**)&hh,    g_hh);
    cudaGetSymbolAddress((void**)&hl,    g_hl);
    cudaGetSymbolAddress((void**)&vTh,   g_vTh);
    cudaGetSymbolAddress((void**)&vTl,   g_vTl);

    cudaFuncSetAttribute(attn_mma_kernel, cudaFuncAttributeMaxDynamicSharedMemorySize, ATTN_SMEM);
    cudaFuncSetAttribute(mma_gemm, cudaFuncAttributeMaxDynamicSharedMemorySize, GEMM_SMEM);
    cudaFuncSetAttribute(moe_gateup, cudaFuncAttributeMaxDynamicSharedMemorySize, GU_SMEM);

    ln_kernel<<<T, 256>>>(hs, l1w, l1b, nullptr, xlnh, xlnl);
    dim3 gproj(D / 128, T / 128, 1);
    mma_gemm<<<gproj, 256, GEMM_SMEM>>>(xlnh, xlnl, wq, q, nullptr, D, D, 0);
    mma_gemm<<<gproj, 256, GEMM_SMEM>>>(xlnh, xlnl, wk, k, nullptr, D, D, 0);
    mma_gemm<<<gproj, 256, GEMM_SMEM>>>(xlnh, xlnl, wv, v, nullptr, D, D, 0);
    rope_split_kernel<<<T, 256>>>();
    transpose_split<<<dim3(D / 32, T / 32, 1), 256>>>(v, vTh, vTl, T, D);
    attn_mma_kernel<<<dim3(T / 64, NH), 128, ATTN_SMEM>>>();
    mma_gemm<<<gproj, 256, GEMM_SMEM>>>(attnh, attnl, wo, hs1, hs, D, D, 1);
    ln_kernel<<<T, 256>>>(hs1, l2w, l2b, xln2, xln2h, xln2l);
    zero_cnt_kernel<<<1, 256>>>();
    router_kernel<<<T, 256>>>(wr);
    scan_kernel<<<1, 32>>>();
    moe_gateup<<<dim3(FF / 64, T / 128, NE), 256, GU_SMEM>>>(xln2h, xln2l, wg, wu);
    dim3 gdown(D / 128, T / 128, NE);
    mma_gemm<<<gdown, 256, GEMM_SMEM>>>(hh, hl, wd, nullptr, nullptr, D, FF, 4);
    combine_kernel<<<(T * D) / 256, 256>>>(out);
    if (out_size > T * D) aux_kernel<<<1, 256>>>(out);
}

// round 15
// speedup vs baseline: 1.0557x; 1.0557x over previous
#include <cuda_runtime.h>
#include <cuda_bf16.h>
#include <math.h>
#include <stdint.h>

#define T 2048
#define D 1024
#define NH 16
#define HD 64
#define NE 8
#define FF 2048

typedef __nv_bfloat16 bf16;

// ---------------- fp32 scratch ----------------
__device__ float g_q[T*D];
__device__ float g_k[T*D];
__device__ float g_v[T*D];
__device__ float g_hs1[T*D];
__device__ float g_xln2[T*D];
__device__ float g_ypart[T*2*D];
__device__ float g_probs[T*NE];
__device__ float g_lse[T];
__device__ float g_gatew[T*2];
__device__ int   g_topk[T*2];
__device__ int   g_ecnt[NE];
__device__ int   g_eoff[NE];
__device__ int   g_elist[NE*T];
// ---------------- bf16 hi/lo operand arrays ----------------
__device__ bf16 g_xlnh[T*D],  g_xlnl[T*D];
__device__ bf16 g_xln2h[T*D], g_xln2l[T*D];
__device__ bf16 g_attnh[T*D], g_attnl[T*D];
__device__ bf16 g_qh[T*D], g_ql[T*D], g_kh[T*D], g_kl[T*D];
__device__ bf16 g_vTh[D*T], g_vTl[D*T];
__device__ bf16 g_hh[(2*T+128)*FF], g_hl[(2*T+128)*FF];

// ---------------- helpers ----------------
__device__ __forceinline__ uint32_t smem_u32(const void* p) {
    uint32_t a;
    asm("{ .reg .u64 t; cvta.to.shared.u64 t, %1; cvt.u32.u64 %0, t; }" : "=r"(a) : "l"(p));
    return a;
}
__device__ __forceinline__ void ldm_x4(uint32_t* r, uint32_t addr) {
    asm volatile("ldmatrix.sync.aligned.m8n8.x4.shared.b16 {%0,%1,%2,%3}, [%4];"
        : "=r"(r[0]), "=r"(r[1]), "=r"(r[2]), "=r"(r[3]) : "r"(addr));
}
__device__ __forceinline__ void ldm_x4_trans(uint32_t* r, uint32_t addr) {
    asm volatile("ldmatrix.sync.aligned.m8n8.x4.trans.shared.b16 {%0,%1,%2,%3}, [%4];"
        : "=r"(r[0]), "=r"(r[1]), "=r"(r[2]), "=r"(r[3]) : "r"(addr));
}
__device__ __forceinline__ void mma_bf16(float* c, const uint32_t* a, uint32_t b0, uint32_t b1) {
    asm volatile(
        "mma.sync.aligned.m16n8k16.row.col.f32.bf16.bf16.f32 "
        "{%0,%1,%2,%3}, {%4,%5,%6,%7}, {%8,%9}, {%0,%1,%2,%3};"
        : "+f"(c[0]), "+f"(c[1]), "+f"(c[2]), "+f"(c[3])
        : "r"(a[0]), "r"(a[1]), "r"(a[2]), "r"(a[3]), "r"(b0), "r"(b1));
}
__device__ __forceinline__ uint32_t pack_bf16(float a, float b) {
    __nv_bfloat162 t;
    t.x = __float2bfloat16(a); t.y = __float2bfloat16(b);
    return *(uint32_t*)&t;
}
__device__ __forceinline__ void split_store(bf16* ph, bf16* pl, size_t idx, float v0, float v1) {
    __nv_bfloat162 h, l;
    h.x = __float2bfloat16(v0); h.y = __float2bfloat16(v1);
    l.x = __float2bfloat16(v0 - __bfloat162float(h.x));
    l.y = __float2bfloat16(v1 - __bfloat162float(h.y));
    *(__nv_bfloat162*)&ph[idx] = h;
    *(__nv_bfloat162*)&pl[idx] = l;
}
__device__ __forceinline__ void cvt_split_u2(float4 b, uint2& hv, uint2& lv) {
    __nv_bfloat162 h0, h1, l0, l1;
    h0.x = __float2bfloat16(b.x); h0.y = __float2bfloat16(b.y);
    h1.x = __float2bfloat16(b.z); h1.y = __float2bfloat16(b.w);
    l0.x = __float2bfloat16(b.x - __bfloat162float(h0.x));
    l0.y = __float2bfloat16(b.y - __bfloat162float(h0.y));
    l1.x = __float2bfloat16(b.z - __bfloat162float(h1.x));
    l1.y = __float2bfloat16(b.w - __bfloat162float(h1.y));
    hv.x = *(uint32_t*)&h0; hv.y = *(uint32_t*)&h1;
    lv.x = *(uint32_t*)&l0; lv.y = *(uint32_t*)&l1;
}
#define CP_ASYNC16(sa, gp) \
    asm volatile("cp.async.cg.shared.global [%0], [%1], 16;" :: "r"(sa), "l"(gp))
#define CP_COMMIT() asm volatile("cp.async.commit_group;" ::: "memory")
#define CP_WAIT1() asm volatile("cp.async.wait_group 1;" ::: "memory")

// ---------------- transpose + bf16 split (V only) ----------------
__global__ __launch_bounds__(256) void transpose_split(const float* __restrict__ in,
                                                       bf16* __restrict__ oh,
                                                       bf16* __restrict__ ol,
                                                       int R, int C) {
    __shared__ float tile[32][33];
    int c0 = blockIdx.x * 32, r0 = blockIdx.y * 32;
    int tx = threadIdx.x & 31, ty = threadIdx.x >> 5;
    for (int i = ty; i < 32; i += 8)
        tile[i][tx] = in[(size_t)(r0 + i) * C + c0 + tx];
    __syncthreads();
    for (int i = ty; i < 32; i += 8) {
        float v = tile[tx][i];
        bf16 h = __float2bfloat16(v);
        oh[(size_t)(c0 + i) * R + r0 + tx] = h;
        ol[(size_t)(c0 + i) * R + r0 + tx] = __float2bfloat16(v - __bfloat162float(h));
    }
}

// ---------------- bf16x3 double-buffered tensor-core GEMM (R13 proven) ----------------
// mode 0: C=A@B   1: +res   4: A=compact g_hh rows, weighted scatter to g_ypart
#define STRIDE 40
#define BSTRIDE 136
#define ABUF 10240
#define BBUF 8704
#define GEMM_SMEM (4*ABUF + 4*BBUF)
__global__ __launch_bounds__(256, 1) void mma_gemm(const bf16* __restrict__ Ah_,
                                                   const bf16* __restrict__ Al_,
                                                   const float* __restrict__ B,
                                                   float* __restrict__ C,
                                                   const float* __restrict__ res,
                                                   int N, int K, int mode) {
    extern __shared__ char dyn[];
    uint32_t aAh = smem_u32(dyn);
    uint32_t aAl = aAh + 2 * ABUF;
    uint32_t aBh = aAh + 4 * ABUF;
    uint32_t aBl = aBh + 2 * BBUF;
    uint32_t* sAh32 = (uint32_t*)dyn;
    uint32_t* sAl32 = (uint32_t*)(dyn + 2 * ABUF);
    bf16* sBh = (bf16*)(dyn + 4 * ABUF);
    bf16* sBl = (bf16*)(dyn + 4 * ABUF + 2 * BBUF);
    __shared__ float swgt[128];
    __shared__ int sdst[128];

    int tid = threadIdx.x, wid = tid >> 5, lane = tid & 31;
    int e = blockIdx.z;
    int cnt = 0, goff = 0;
    int row0 = blockIdx.y * 128, col0 = blockIdx.x * 128;
    int K2 = K >> 1;
    const uint32_t* Ah = (const uint32_t*)Ah_;
    const uint32_t* Al = (const uint32_t*)Al_;
    if (mode == 4) {
        cnt = g_ecnt[e]; goff = g_eoff[e];
        if (row0 >= cnt) return;
        if (tid < 128) {
            int slot = row0 + tid;
            if (slot < cnt) {
                int p = g_elist[e * T + slot];
                int tt = p >> 1, ks = p & 1;
                swgt[tid] = g_gatew[tt * 2 + ks];
                sdst[tid] = tt * 2 + ks;
            } else { swgt[tid] = 0.f; sdst[tid] = -1; }
        }
        B += (size_t)e * (size_t)K * (size_t)N;
        __syncthreads();
    }

    int wr = wid & 3, wc = wid >> 2;
    float acc[2][8][4] = {};

    int nchunks = K >> 5;
    uint4 aRh4[2], aRl4[2];
    float4 bR[4];

    auto loadRegs = [&](int chunk) {
        int kc0 = chunk * 16;
        #pragma unroll
        for (int f = 0; f < 2; f++) {
            int fi = tid + f * 256; int r = fi >> 2, c4 = fi & 3;
            size_t arow = (mode == 4) ? (size_t)(goff + row0 + r) : (size_t)(row0 + r);
            aRh4[f] = *(const uint4*)&Ah[arow * K2 + kc0 + c4 * 4];
            aRl4[f] = *(const uint4*)&Al[arow * K2 + kc0 + c4 * 4];
        }
        int kr0 = chunk * 32;
        #pragma unroll
        for (int f = 0; f < 4; f++) {
            int fi = tid + f * 256; int r = fi >> 5, c = (fi & 31) * 4;
            bR[f] = *(const float4*)&B[(size_t)(kr0 + r) * N + col0 + c];
        }
    };
    auto storeRegs = [&](int buf) {
        int ao = buf * (ABUF / 4);
        #pragma unroll
        for (int f = 0; f < 2; f++) {
            int fi = tid + f * 256; int r = fi >> 2, c4 = fi & 3;
            int si = ao + r * (STRIDE / 2) + c4 * 4;
            *(uint4*)&sAh32[si] = aRh4[f];
            *(uint4*)&sAl32[si] = aRl4[f];
        }
        int bo = buf * (BBUF / 2);
        #pragma unroll
        for (int f = 0; f < 4; f++) {
            int fi = tid + f * 256; int r = fi >> 5, c = (fi & 31) * 4;
            int si = bo + r * BSTRIDE + c;
            uint2 hv, lv;
            cvt_split_u2(bR[f], hv, lv);
            *(uint2*)&sBh[si] = hv;
            *(uint2*)&sBl[si] = lv;
        }
    };

    int lrow = lane & 15;
    int lcol8 = (lane >> 4) << 3;
    int tb_k = (lane & 7) + ((lane >> 4) << 3);
    int tb_n = ((lane >> 3) & 1) << 3;

    loadRegs(0);
    storeRegs(0);
    __syncthreads();

    for (int i = 0; i < nchunks; i++) {
        int b = i & 1;
        if (i + 1 < nchunks) loadRegs(i + 1);
        uint32_t Aoff = (uint32_t)(b * ABUF);
        uint32_t Boff = (uint32_t)(b * BBUF);
        #pragma unroll
        for (int ks = 0; ks < 2; ks++) {
            int k0 = ks * 16;
            uint32_t ah[2][4], al[2][4];
            #pragma unroll
            for (int im = 0; im < 2; im++) {
                uint32_t off = (uint32_t)((wr * 32 + im * 16 + lrow) * STRIDE + k0 + lcol8) * 2 + Aoff;
                ldm_x4(ah[im], aAh + off);
                ldm_x4(al[im], aAl + off);
            }
            #pragma unroll
            for (int np = 0; np < 4; np++) {
                uint32_t off = (uint32_t)((k0 + tb_k) * BSTRIDE + wc * 64 + np * 16 + tb_n) * 2 + Boff;
                uint32_t bh[4], bl[4];
                ldm_x4_trans(bh, aBh + off);
                ldm_x4_trans(bl, aBl + off);
                #pragma unroll
                for (int im = 0; im < 2; im++) {
                    mma_bf16(acc[im][np * 2],     ah[im], bh[0], bh[2]);
                    mma_bf16(acc[im][np * 2],     ah[im], bl[0], bl[2]);
                    mma_bf16(acc[im][np * 2],     al[im], bh[0], bh[2]);
                    mma_bf16(acc[im][np * 2 + 1], ah[im], bh[1], bh[3]);
                    mma_bf16(acc[im][np * 2 + 1], ah[im], bl[1], bl[3]);
                    mma_bf16(acc[im][np * 2 + 1], al[im], bh[1], bh[3]);
                }
            }
        }
        if (i + 1 < nchunks) storeRegs(b ^ 1);
        __syncthreads();
    }

    // ---------------- epilogue ----------------
    #pragma unroll
    for (int im = 0; im < 2; im++) {
        #pragma unroll
        for (int nt = 0; nt < 8; nt++) {
            int col = wc * 64 + nt * 8 + (lane & 3) * 2;
            int n = col0 + col;
            #pragma unroll
            for (int half = 0; half < 2; half++) {
                int slot = wr * 32 + im * 16 + (lane >> 2) + half * 8;
                float v0 = acc[im][nt][half * 2], v1 = acc[im][nt][half * 2 + 1];
                if (mode == 0) {
                    *(float2*)&C[(size_t)(row0 + slot) * N + n] = make_float2(v0, v1);
                } else if (mode == 1) {
                    size_t di = (size_t)(row0 + slot) * N + n;
                    float2 rr = *(const float2*)&res[di];
                    *(float2*)&C[di] = make_float2(v0 + rr.x, v1 + rr.y);
                } else {
                    if (row0 + slot < cnt && sdst[slot] >= 0) {
                        float w = swgt[slot];
                        *(float2*)&g_ypart[(size_t)sdst[slot] * D + n] = make_float2(w * v0, w * v1);
                    }
                }
            }
        }
    }
}

// ---------------- fused MoE gate+up GEMM: h = silu(x@Wg) * (x@Wu) ----------------
#define BS2 72
#define GBUF 4608
#define GU_SMEM (4*ABUF + 8*GBUF)
__global__ __launch_bounds__(256, 1) void moe_gateup(const bf16* __restrict__ Ah_,
                                                     const bf16* __restrict__ Al_,
                                                     const float* __restrict__ Wg,
                                                     const float* __restrict__ Wu) {
    extern __shared__ char dyn[];
    uint32_t aAh = smem_u32(dyn);
    uint32_t aAl = aAh + 2 * ABUF;
    uint32_t aGh = aAh + 4 * ABUF;
    uint32_t aGl = aGh + 2 * GBUF;
    uint32_t aUh = aGh + 4 * GBUF;
    uint32_t aUl = aGh + 6 * GBUF;
    uint32_t* sAh32 = (uint32_t*)dyn;
    uint32_t* sAl32 = (uint32_t*)(dyn + 2 * ABUF);
    bf16* sGh = (bf16*)(dyn + 4 * ABUF);
    bf16* sGl = (bf16*)(dyn + 4 * ABUF + 2 * GBUF);
    bf16* sUh = (bf16*)(dyn + 4 * ABUF + 4 * GBUF);
    bf16* sUl = (bf16*)(dyn + 4 * ABUF + 6 * GBUF);
    __shared__ int toks[128];

    int tid = threadIdx.x, wid = tid >> 5, lane = tid & 31;
    int e = blockIdx.z;
    int cnt = g_ecnt[e], goff = g_eoff[e];
    int row0 = blockIdx.y * 128, col0 = blockIdx.x * 64;
    if (row0 >= cnt) return;
    Wg += (size_t)e * D * FF;
    Wu += (size_t)e * D * FF;
    if (tid < 128) {
        int slot = row0 + tid;
        toks[tid] = (slot < cnt) ? (g_elist[e * T + slot] >> 1) : 0;
    }
    __syncthreads();

    const uint32_t* Ah = (const uint32_t*)Ah_;
    const uint32_t* Al = (const uint32_t*)Al_;
    int wr = wid & 3, wc = wid >> 2;
    float aG[2][4][4] = {}, aU[2][4][4] = {};

    uint4 aRh4[2], aRl4[2];
    float4 gR[2], uR[2];
    auto loadRegs = [&](int chunk) {
        int kc0 = chunk * 16;
        #pragma unroll
        for (int f = 0; f < 2; f++) {
            int fi = tid + f * 256; int r = fi >> 2, c4 = fi & 3;
            size_t arow = (size_t)toks[r];
            aRh4[f] = *(const uint4*)&Ah[arow * (D / 2) + kc0 + c4 * 4];
            aRl4[f] = *(const uint4*)&Al[arow * (D / 2) + kc0 + c4 * 4];
        }
        int kr0 = chunk * 32;
        #pragma unroll
        for (int f = 0; f < 2; f++) {
            int fi = tid + f * 256; int r = fi >> 4, c = (fi & 15) * 4;
            gR[f] = *(const float4*)&Wg[(size_t)(kr0 + r) * FF + col0 + c];
            uR[f] = *(const float4*)&Wu[(size_t)(kr0 + r) * FF + col0 + c];
        }
    };
    auto storeRegs = [&](int buf) {
        int ao = buf * (ABUF / 4);
        #pragma unroll
        for (int f = 0; f < 2; f++) {
            int fi = tid + f * 256; int r = fi >> 2, c4 = fi & 3;
            int si = ao + r * (STRIDE / 2) + c4 * 4;
            *(uint4*)&sAh32[si] = aRh4[f];
            *(uint4*)&sAl32[si] = aRl4[f];
        }
        int bo = buf * (GBUF / 2);
        #pragma unroll
        for (int f = 0; f < 2; f++) {
            int fi = tid + f * 256; int r = fi >> 4, c = (fi & 15) * 4;
            int si = bo + r * BS2 + c;
            uint2 hv, lv;
            cvt_split_u2(gR[f], hv, lv);
            *(uint2*)&sGh[si] = hv; *(uint2*)&sGl[si] = lv;
            cvt_split_u2(uR[f], hv, lv);
            *(uint2*)&sUh[si] = hv; *(uint2*)&sUl[si] = lv;
        }
    };

    int lrow = lane & 15;
    int lcol8 = (lane >> 4) << 3;
    int tb_k = (lane & 7) + ((lane >> 4) << 3);
    int tb_n = ((lane >> 3) & 1) << 3;

    loadRegs(0);
    storeRegs(0);
    __syncthreads();

    int nchunks = D >> 5;
    for (int i = 0; i < nchunks; i++) {
        int b = i & 1;
        if (i + 1 < nchunks) loadRegs(i + 1);
        uint32_t Aoff = (uint32_t)(b * ABUF);
        uint32_t Boff = (uint32_t)(b * GBUF);
        #pragma unroll
        for (int ks = 0; ks < 2; ks++) {
            int k0 = ks * 16;
            uint32_t ah[2][4], al[2][4];
            #pragma unroll
            for (int im = 0; im < 2; im++) {
                uint32_t off = (uint32_t)((wr * 32 + im * 16 + lrow) * STRIDE + k0 + lcol8) * 2 + Aoff;
                ldm_x4(ah[im], aAh + off);
                ldm_x4(al[im], aAl + off);
            }
            #pragma unroll
            for (int np = 0; np < 2; np++) {
                uint32_t off = (uint32_t)((k0 + tb_k) * BS2 + wc * 32 + np * 16 + tb_n) * 2 + Boff;
                uint32_t bh[4], bl[4];
                ldm_x4_trans(bh, aGh + off);
                ldm_x4_trans(bl, aGl + off);
                #pragma unroll
                for (int im = 0; im < 2; im++) {
                    mma_bf16(aG[im][np * 2],     ah[im], bh[0], bh[2]);
                    mma_bf16(aG[im][np * 2],     ah[im], bl[0], bl[2]);
                    mma_bf16(aG[im][np * 2],     al[im], bh[0], bh[2]);
                    mma_bf16(aG[im][np * 2 + 1], ah[im], bh[1], bh[3]);
                    mma_bf16(aG[im][np * 2 + 1], ah[im], bl[1], bl[3]);
                    mma_bf16(aG[im][np * 2 + 1], al[im], bh[1], bh[3]);
                }
                ldm_x4_trans(bh, aUh + off);
                ldm_x4_trans(bl, aUl + off);
                #pragma unroll
                for (int im = 0; im < 2; im++) {
                    mma_bf16(aU[im][np * 2],     ah[im], bh[0], bh[2]);
                    mma_bf16(aU[im][np * 2],     ah[im], bl[0], bl[2]);
                    mma_bf16(aU[im][np * 2],     al[im], bh[0], bh[2]);
                    mma_bf16(aU[im][np * 2 + 1], ah[im], bh[1], bh[3]);
                    mma_bf16(aU[im][np * 2 + 1], ah[im], bl[1], bl[3]);
                    mma_bf16(aU[im][np * 2 + 1], al[im], bh[1], bh[3]);
                }
            }
        }
        if (i + 1 < nchunks) storeRegs(b ^ 1);
        __syncthreads();
    }

    #pragma unroll
    for (int im = 0; im < 2; im++) {
        #pragma unroll
        for (int nt = 0; nt < 4; nt++) {
            int n = col0 + wc * 32 + nt * 8 + (lane & 3) * 2;
            #pragma unroll
            for (int half = 0; half < 2; half++) {
                int slot = wr * 32 + im * 16 + (lane >> 2) + half * 8;
                if (row0 + slot < cnt) {
                    float gg0 = aG[im][nt][half * 2], gg1 = aG[im][nt][half * 2 + 1];
                    float u0 = aU[im][nt][half * 2], u1 = aU[im][nt][half * 2 + 1];
                    float h0 = u0 * (gg0 / (1.f + __expf(-gg0)));
                    float h1 = u1 * (gg1 / (1.f + __expf(-gg1)));
                    split_store(g_hh, g_hl, (size_t)(goff + row0 + slot) * FF + n, h0, h1);
                }
            }
        }
    }
}

// ---------------- LayerNorm (+ bf16 hi/lo split out) ----------------
__global__ __launch_bounds__(256) void ln_kernel(const float* __restrict__ x,
                                                 const float* __restrict__ w,
                                                 const float* __restrict__ b,
                                                 float* __restrict__ out,
                                                 bf16* __restrict__ oh,
                                                 bf16* __restrict__ ol) {
    int t = blockIdx.x;
    const float* row = x + (size_t)t * D;
    __shared__ float sh[256];
    int tid = threadIdx.x;
    float s = 0.f;
    for (int i = tid; i < D; i += 256) s += row[i];
    sh[tid] = s; __syncthreads();
    for (int o = 128; o; o >>= 1) { if (tid < o) sh[tid] += sh[tid + o]; __syncthreads(); }
    float mean = sh[0] / D;
    __syncthreads();
    float v = 0.f;
    for (int i = tid; i < D; i += 256) { float dd = row[i] - mean; v += dd * dd; }
    sh[tid] = v; __syncthreads();
    for (int o = 128; o; o >>= 1) { if (tid < o) sh[tid] += sh[tid + o]; __syncthreads(); }
    float rstd = rsqrtf(sh[0] / D + 1e-5f);
    for (int i2 = tid; i2 < D / 2; i2 += 256) {
        int i = i2 * 2;
        float y0 = (row[i] - mean) * rstd * w[i] + b[i];
        float y1 = (row[i + 1] - mean) * rstd * w[i + 1] + b[i + 1];
        size_t di = (size_t)t * D + i;
        if (out) *(float2*)&out[di] = make_float2(y0, y1);
        split_store(oh, ol, di, y0, y1);
    }
}

// ---------------- RoPE + bf16 split of q, k ----------------
__global__ __launch_bounds__(256) void rope_split_kernel() {
    int t = blockIdx.x;
    for (int p = threadIdx.x; p < D / 2; p += 256) {
        int head = p >> 5;
        int i = p & 31;
        int i1 = t * D + head * HD + i;
        int i2 = i1 + 32;
        float inv = expf(-(2.0f * i / HD) * 9.210340371976184f);
        float fr = (float)t * inv;
        float c = cosf(fr), s = sinf(fr);
        float q1 = g_q[i1], q2 = g_q[i2];
        float k1 = g_k[i1], k2 = g_k[i2];
        float qa = q1 * c - q2 * s, qb = q2 * c + q1 * s;
        float ka = k1 * c - k2 * s, kb = k2 * c + k1 * s;
        bf16 h;
        h = __float2bfloat16(qa); g_qh[i1] = h; g_ql[i1] = __float2bfloat16(qa - __bfloat162float(h));
        h = __float2bfloat16(qb); g_qh[i2] = h; g_ql[i2] = __float2bfloat16(qb - __bfloat162float(h));
        h = __float2bfloat16(ka); g_kh[i1] = h; g_kl[i1] = __float2bfloat16(ka - __bfloat162float(h));
        h = __float2bfloat16(kb); g_kh[i2] = h; g_kl[i2] = __float2bfloat16(kb - __bfloat162float(h));
    }
}

// ---------------- tensor-core flash attention: 3-stage cp.async K/V pipeline ----------------
#define AS 72
#define ABUFSZ 36864
#define ATTN_SMEM (3 * ABUFSZ)
__global__ __launch_bounds__(128) void attn_mma_kernel() {
    extern __shared__ bf16 asm_[];
    int qt = blockIdx.x, h = blockIdx.y;
    int tid = threadIdx.x, w = tid >> 5, lane = tid & 31;
    int lrow = lane & 15, lcol8 = (lane >> 4) << 3;
    uint32_t aBase = smem_u32(asm_);
    uint32_t* sKBh32 = (uint32_t*)asm_;
    uint32_t* sKBl32 = (uint32_t*)((char*)asm_ + 9216);
    const uint32_t* qh32 = (const uint32_t*)g_qh;
    const uint32_t* ql32 = (const uint32_t*)g_ql;
    const uint32_t* kh32 = (const uint32_t*)g_kh;
    const uint32_t* kl32 = (const uint32_t*)g_kl;
    const uint32_t* vth32 = (const uint32_t*)g_vTh;
    const uint32_t* vtl32 = (const uint32_t*)g_vTl;

    // stage Q through buffer-0 K arrays, hoist Q fragments
    for (int i = tid; i < 64 * 32; i += 128) {
        int r = i >> 5, c = i & 31;
        sKBh32[r * (AS / 2) + c] = qh32[(size_t)(qt * 64 + r) * (D / 2) + h * 32 + c];
        sKBl32[r * (AS / 2) + c] = ql32[(size_t)(qt * 64 + r) * (D / 2) + h * 32 + c];
    }
    __syncthreads();
    uint32_t qah[4][4], qal[4][4];
    #pragma unroll
    for (int kc = 0; kc < 4; kc++) {
        uint32_t off = (uint32_t)((w * 16 + lrow) * AS + kc * 16 + lcol8) * 2;
        ldm_x4(qah[kc], aBase + off);
        ldm_x4(qal[kc], aBase + 9216 + off);
    }
    __syncthreads();

    int nkt = qt + 1;
    // always commits a group (empty if kt >= nkt) so exactly 2 groups are
    // outstanding at each wait -> wait_group 1 guarantees tile kt resident
    auto issue_tile = [&](int kt) {
        if (kt < nkt) {
            int kb = kt * 64;
            uint32_t base = aBase + (uint32_t)(kt % 3) * ABUFSZ;
            #pragma unroll
            for (int f = 0; f < 4; f++) {
                int j = tid + f * 128;
                int r = j >> 3, c4 = (j & 7) * 4;
                uint32_t so = (uint32_t)(r * (AS / 2) + c4) * 4;
                CP_ASYNC16(base + so,         kh32 + (size_t)(kb + r) * (D / 2) + h * 32 + c4);
                CP_ASYNC16(base + 9216 + so,  kl32 + (size_t)(kb + r) * (D / 2) + h * 32 + c4);
                CP_ASYNC16(base + 18432 + so, vth32 + (size_t)(h * 64 + r) * (T / 2) + (kb >> 1) + c4);
                CP_ASYNC16(base + 27648 + so, vtl32 + (size_t)(h * 64 + r) * (T / 2) + (kb >> 1) + c4);
            }
        }
        CP_COMMIT();
    };

    float O[8][4] = {};
    float m_lo = -1e30f, m_hi = -1e30f, l_lo = 0.f, l_hi = 0.f;
    int row_lo = qt * 64 + w * 16 + (lane >> 2);
    int row_hi = row_lo + 8;
    issue_tile(0);
    issue_tile(1);
    for (int kt = 0; kt < nkt; kt++) {
        CP_WAIT1();
        __syncthreads();
        issue_tile(kt + 2);
        uint32_t bb = aBase + (uint32_t)(kt % 3) * ABUFSZ;
        int kb = kt * 64;
        float S[8][4] = {};
        #pragma unroll
        for (int kc = 0; kc < 4; kc++) {
            #pragma unroll
            for (int jj = 0; jj < 4; jj++) {
                uint32_t off = (uint32_t)((jj * 16 + lrow) * AS + kc * 16 + lcol8) * 2;
                uint32_t bh[4], bl[4];
                ldm_x4(bh, bb + off);
                ldm_x4(bl, bb + 9216 + off);
                mma_bf16(S[2 * jj],     qah[kc], bh[0], bh[2]);
                mma_bf16(S[2 * jj],     qah[kc], bl[0], bl[2]);
                mma_bf16(S[2 * jj],     qal[kc], bh[0], bh[2]);
                mma_bf16(S[2 * jj + 1], qah[kc], bh[1], bh[3]);
                mma_bf16(S[2 * jj + 1], qah[kc], bl[1], bl[3]);
                mma_bf16(S[2 * jj + 1], qal[kc], bh[1], bh[3]);
            }
        }
        bool diag = (kt == qt);
        float mt_lo = -1e30f, mt_hi = -1e30f;
        #pragma unroll
        for (int j = 0; j < 8; j++) {
            int c0 = kb + j * 8 + ((lane & 3) << 1);
            float s0 = S[j][0] * 0.125f, s1 = S[j][1] * 0.125f;
            float s2 = S[j][2] * 0.125f, s3 = S[j][3] * 0.125f;
            if (diag) {
                if (c0 > row_lo) s0 = -1e30f;
                if (c0 + 1 > row_lo) s1 = -1e30f;
                if (c0 > row_hi) s2 = -1e30f;
                if (c0 + 1 > row_hi) s3 = -1e30f;
            }
            S[j][0] = s0; S[j][1] = s1; S[j][2] = s2; S[j][3] = s3;
            mt_lo = fmaxf(mt_lo, fmaxf(s0, s1));
            mt_hi = fmaxf(mt_hi, fmaxf(s2, s3));
        }
        mt_lo = fmaxf(mt_lo, __shfl_xor_sync(0xffffffff, mt_lo, 1));
        mt_lo = fmaxf(mt_lo, __shfl_xor_sync(0xffffffff, mt_lo, 2));
        mt_hi = fmaxf(mt_hi, __shfl_xor_sync(0xffffffff, mt_hi, 1));
        mt_hi = fmaxf(mt_hi, __shfl_xor_sync(0xffffffff, mt_hi, 2));
        float mn_lo = fmaxf(m_lo, mt_lo), mn_hi = fmaxf(m_hi, mt_hi);
        float co_lo = __expf(m_lo - mn_lo), co_hi = __expf(m_hi - mn_hi);
        l_lo *= co_lo; l_hi *= co_hi;
        #pragma unroll
        for (int j = 0; j < 8; j++) {
            O[j][0] *= co_lo; O[j][1] *= co_lo;
            O[j][2] *= co_hi; O[j][3] *= co_hi;
            S[j][0] = __expf(S[j][0] - mn_lo);
            S[j][1] = __expf(S[j][1] - mn_lo);
            S[j][2] = __expf(S[j][2] - mn_hi);
            S[j][3] = __expf(S[j][3] - mn_hi);
            l_lo += S[j][0] + S[j][1];
            l_hi += S[j][2] + S[j][3];
        }
        m_lo = mn_lo; m_hi = mn_hi;
        #pragma unroll
        for (int kc = 0; kc < 4; kc++) {
            uint32_t pah[4], pal[4];
            {
                float p0 = S[2 * kc][0], p1 = S[2 * kc][1], p2 = S[2 * kc][2], p3 = S[2 * kc][3];
                float q0 = S[2 * kc + 1][0], q1 = S[2 * kc + 1][1], q2 = S[2 * kc + 1][2], q3 = S[2 * kc + 1][3];
                pah[0] = pack_bf16(p0, p1); pah[1] = pack_bf16(p2, p3);
                pah[2] = pack_bf16(q0, q1); pah[3] = pack_bf16(q2, q3);
                __nv_bfloat162 t;
                t = *(__nv_bfloat162*)&pah[0];
                pal[0] = pack_bf16(p0 - __bfloat162float(t.x), p1 - __bfloat162float(t.y));
                t = *(__nv_bfloat162*)&pah[1];
                pal[1] = pack_bf16(p2 - __bfloat162float(t.x), p3 - __bfloat162float(t.y));
                t = *(__nv_bfloat162*)&pah[2];
                pal[2] = pack_bf16(q0 - __bfloat162float(t.x), q1 - __bfloat162float(t.y));
                t = *(__nv_bfloat162*)&pah[3];
                pal[3] = pack_bf16(q2 - __bfloat162float(t.x), q3 - __bfloat162float(t.y));
            }
            #pragma unroll
            for (int dd = 0; dd < 4; dd++) {
                uint32_t off = (uint32_t)((dd * 16 + lrow) * AS + kc * 16 + lcol8) * 2;
                uint32_t vh[4], vl[4];
                ldm_x4(vh, bb + 18432 + off);
                ldm_x4(vl, bb + 27648 + off);
                mma_bf16(O[2 * dd],     pah, vh[0], vh[2]);
                mma_bf16(O[2 * dd],     pah, vl[0], vl[2]);
                mma_bf16(O[2 * dd],     pal, vh[0], vh[2]);
                mma_bf16(O[2 * dd + 1], pah, vh[1], vh[3]);
                mma_bf16(O[2 * dd + 1], pah, vl[1], vl[3]);
                mma_bf16(O[2 * dd + 1], pal, vh[1], vh[3]);
            }
        }
    }
    l_lo += __shfl_xor_sync(0xffffffff, l_lo, 1);
    l_lo += __shfl_xor_sync(0xffffffff, l_lo, 2);
    l_hi += __shfl_xor_sync(0xffffffff, l_hi, 1);
    l_hi += __shfl_xor_sync(0xffffffff, l_hi, 2);
    float inv_lo = 1.f / l_lo, inv_hi = 1.f / l_hi;
    #pragma unroll
    for (int j = 0; j < 8; j++) {
        int col = h * 64 + j * 8 + ((lane & 3) << 1);
        split_store(g_attnh, g_attnl, (size_t)row_lo * D + col, O[j][0] * inv_lo, O[j][1] * inv_lo);
        split_store(g_attnh, g_attnl, (size_t)row_hi * D + col, O[j][2] * inv_hi, O[j][3] * inv_hi);
    }
}

// ---------------- router ----------------
__global__ __launch_bounds__(256) void zero_cnt_kernel() {
    if (threadIdx.x < NE) g_ecnt[threadIdx.x] = 0;
}

__global__ __launch_bounds__(256) void router_kernel(const float* __restrict__ wr) {
    int t = blockIdx.x;
    int tid = threadIdx.x, lane = tid & 31, w = tid >> 5;
    const float* x = g_xln2 + (size_t)t * D;
    float s = 0.f;
    for (int d = lane; d < D; d += 32) s += x[d] * wr[d * NE + w];
    #pragma unroll
    for (int o = 16; o; o >>= 1) s += __shfl_xor_sync(0xffffffff, s, o);
    __shared__ float lg[NE];
    if (lane == 0) lg[w] = s;
    __syncthreads();
    if (tid == 0) {
        float mx = -1e30f;
        #pragma unroll
        for (int e = 0; e < NE; e++) mx = fmaxf(mx, lg[e]);
        float ex[NE], sum = 0.f;
        #pragma unroll
        for (int e = 0; e < NE; e++) { ex[e] = expf(lg[e] - mx); sum += ex[e]; }
        g_lse[t] = mx + logf(sum);
        float pr[NE];
        #pragma unroll
        for (int e = 0; e < NE; e++) { pr[e] = ex[e] / sum; g_probs[t * NE + e] = pr[e]; }
        int e0 = 0; float b0 = pr[0];
        #pragma unroll
        for (int e = 1; e < NE; e++) if (pr[e] > b0) { b0 = pr[e]; e0 = e; }
        int e1 = -1; float b1 = -1.f;
        #pragma unroll
        for (int e = 0; e < NE; e++) if (e != e0 && pr[e] > b1) { b1 = pr[e]; e1 = e; }
        float ws = b0 + b1;
        g_gatew[t * 2 + 0] = b0 / ws;
        g_gatew[t * 2 + 1] = b1 / ws;
        g_topk[t * 2 + 0] = e0;
        g_topk[t * 2 + 1] = e1;
        int s0 = atomicAdd(&g_ecnt[e0], 1); g_elist[e0 * T + s0] = (t << 1) | 0;
        int s1 = atomicAdd(&g_ecnt[e1], 1); g_elist[e1 * T + s1] = (t << 1) | 1;
    }
}

__global__ void scan_kernel() {
    if (threadIdx.x == 0) {
        int o = 0;
        for (int e = 0; e < NE; e++) { g_eoff[e] = o; o += g_ecnt[e]; }
    }
}

// ---------------- final combine ----------------
__global__ __launch_bounds__(256) void combine_kernel(float* __restrict__ out) {
    int i = blockIdx.x * 256 + threadIdx.x;
    int t = i >> 10, d = i & 1023;
    out[i] = g_hs1[i] + g_ypart[(size_t)(t * 2) * D + d] + g_ypart[(size_t)(t * 2 + 1) * D + d];
}

// ---------------- aux losses ----------------
__global__ __launch_bounds__(256) void aux_kernel(float* __restrict__ out) {
    __shared__ float sh[256];
    __shared__ float totps[NE];
    __shared__ int totcnt[NE];
    __shared__ float zsave;
    int tid = threadIdx.x;
    if (tid < NE) totcnt[tid] = 0;
    float z = 0.f, ps[NE]; int cnt[NE];
    #pragma unroll
    for (int e = 0; e < NE; e++) { ps[e] = 0.f; cnt[e] = 0; }
    for (int t = tid; t < T; t += 256) {
        float l = g_lse[t]; z += l * l;
        #pragma unroll
        for (int e = 0; e < NE; e++) ps[e] += g_probs[t * NE + e];
        cnt[g_topk[t * 2]]++; cnt[g_topk[t * 2 + 1]]++;
    }
    sh[tid] = z; __syncthreads();
    for (int o = 128; o; o >>= 1) { if (tid < o) sh[tid] += sh[tid + o]; __syncthreads(); }
    if (tid == 0) zsave = sh[0];
    __syncthreads();
    for (int e = 0; e < NE; e++) {
        sh[tid] = ps[e]; __syncthreads();
        for (int o = 128; o; o >>= 1) { if (tid < o) sh[tid] += sh[tid + o]; __syncthreads(); }
        if (tid == 0) totps[e] = sh[0];
        __syncthreads();
        atomicAdd(&totcnt[e], cnt[e]);
    }
    __syncthreads();
    if (tid == 0) {
        float zl = 0.001f * zsave / T;
        float lb = 0.f;
        for (int e = 0; e < NE; e++) lb += ((float)totcnt[e] / T) * (totps[e] / T);
        out[T * D] = zl + 0.01f * lb;
    }
}

// ---------------- launch ----------------
extern "C" void kernel_launch(void* const* d_in, const int* in_sizes, int n_in,
                              void* d_out, int out_size) {
    const float* hs  = (const float*)d_in[0];
    const float* l1w = (const float*)d_in[3];
    const float* l1b = (const float*)d_in[4];
    const float* l2w = (const float*)d_in[5];
    const float* l2b = (const float*)d_in[6];
    const float* wq  = (const float*)d_in[7];
    const float* wk  = (const float*)d_in[8];
    const float* wv  = (const float*)d_in[9];
    const float* wo  = (const float*)d_in[10];
    const float* wr  = (const float*)d_in[11];
    const float* wg  = (const float*)d_in[12];
    const float* wu  = (const float*)d_in[13];
    const float* wd  = (const float*)d_in[14];
    float* out = (float*)d_out;

    float *q, *k, *v, *hs1, *xln2;
    bf16 *xlnh, *xlnl, *xln2h, *xln2l, *attnh, *attnl, *hh, *hl, *vTh, *vTl;
    cudaGetSymbolAddress((void**)&q,     g_q);
    cudaGetSymbolAddress((void**)&k,     g_k);
    cudaGetSymbolAddress((void**)&v,     g_v);
    cudaGetSymbolAddress((void**)&hs1,   g_hs1);
    cudaGetSymbolAddress((void**)&xln2,  g_xln2);
    cudaGetSymbolAddress((void**)&xlnh,  g_xlnh);
    cudaGetSymbolAddress((void**)&xlnl,  g_xlnl);
    cudaGetSymbolAddress((void**)&xln2h, g_xln2h);
    cudaGetSymbolAddress((void**)&xln2l, g_xln2l);
    cudaGetSymbolAddress((void**)&attnh, g_attnh);
    cudaGetSymbolAddress((void**)&attnl, g_attnl);
    cudaGetSymbolAddress((void**)&hh,    g_hh);
    cudaGetSymbolAddress((void**)&hl,    g_hl);
    cudaGetSymbolAddress((void**)&vTh,   g_vTh);
    cudaGetSymbolAddress((void**)&vTl,   g_vTl);

    cudaFuncSetAttribute(attn_mma_kernel, cudaFuncAttributeMaxDynamicSharedMemorySize, ATTN_SMEM);
    cudaFuncSetAttribute(mma_gemm, cudaFuncAttributeMaxDynamicSharedMemorySize, GEMM_SMEM);
    cudaFuncSetAttribute(moe_gateup, cudaFuncAttributeMaxDynamicSharedMemorySize, GU_SMEM);

    ln_kernel<<<T, 256>>>(hs, l1w, l1b, nullptr, xlnh, xlnl);
    dim3 gproj(D / 128, T / 128, 1);
    mma_gemm<<<gproj, 256, GEMM_SMEM>>>(xlnh, xlnl, wq, q, nullptr, D, D, 0);
    mma_gemm<<<gproj, 256, GEMM_SMEM>>>(xlnh, xlnl, wk, k, nullptr, D, D, 0);
    mma_gemm<<<gproj, 256, GEMM_SMEM>>>(xlnh, xlnl, wv, v, nullptr, D, D, 0);
    rope_split_kernel<<<T, 256>>>();
    transpose_split<<<dim3(D / 32, T / 32, 1), 256>>>(v, vTh, vTl, T, D);
    attn_mma_kernel<<<dim3(T / 64, NH), 128, ATTN_SMEM>>>();
    mma_gemm<<<gproj, 256, GEMM_SMEM>>>(attnh, attnl, wo, hs1, hs, D, D, 1);
    ln_kernel<<<T, 256>>>(hs1, l2w, l2b, xln2, xln2h, xln2l);
    zero_cnt_kernel<<<1, 256>>>();
    router_kernel<<<T, 256>>>(wr);
    scan_kernel<<<1, 32>>>();
    moe_gateup<<<dim3(FF / 64, T / 128, NE), 256, GU_SMEM>>>(xln2h, xln2l, wg, wu);
    dim3 gdown(D / 128, T / 128, NE);
    mma_gemm<<<gdown, 256, GEMM_SMEM>>>(hh, hl, wd, nullptr, nullptr, D, FF, 4);
    combine_kernel<<<(T * D) / 256, 256>>>(out);
    if (out_size > T * D) aux_kernel<<<1, 256>>>(out);
}

// round 16
// speedup vs baseline: 1.0835x; 1.0264x over previous
#include <cuda_runtime.h>
#include <cuda_bf16.h>
#include <math.h>
#include <stdint.h>

#define T 2048
#define D 1024
#define NH 16
#define HD 64
#define NE 8
#define FF 2048

typedef __nv_bfloat16 bf16;

// ---------------- fp32 scratch ----------------
__device__ float g_q[T*D];
__device__ float g_k[T*D];
__device__ float g_v[T*D];
__device__ float g_hs1[T*D];
__device__ float g_xln2[T*D];
__device__ float g_ypart[T*2*D];
__device__ float g_probs[T*NE];
__device__ float g_lse[T];
__device__ float g_gatew[T*2];
__device__ int   g_topk[T*2];
__device__ int   g_ecnt[NE];
__device__ int   g_eoff[NE];
__device__ int   g_elist[NE*T];
// ---------------- bf16 hi/lo operand arrays ----------------
__device__ bf16 g_xlnh[T*D],  g_xlnl[T*D];
__device__ bf16 g_xln2h[T*D], g_xln2l[T*D];
__device__ bf16 g_attnh[T*D], g_attnl[T*D];
__device__ bf16 g_qh[T*D], g_ql[T*D], g_kh[T*D], g_kl[T*D];
__device__ bf16 g_vTh[D*T], g_vTl[D*T];
__device__ bf16 g_hh[(2*T+128)*FF], g_hl[(2*T+128)*FF];

// ---------------- helpers ----------------
__device__ __forceinline__ uint32_t smem_u32(const void* p) {
    uint32_t a;
    asm("{ .reg .u64 t; cvta.to.shared.u64 t, %1; cvt.u32.u64 %0, t; }" : "=r"(a) : "l"(p));
    return a;
}
__device__ __forceinline__ void ldm_x4(uint32_t* r, uint32_t addr) {
    asm volatile("ldmatrix.sync.aligned.m8n8.x4.shared.b16 {%0,%1,%2,%3}, [%4];"
        : "=r"(r[0]), "=r"(r[1]), "=r"(r[2]), "=r"(r[3]) : "r"(addr));
}
__device__ __forceinline__ void ldm_x4_trans(uint32_t* r, uint32_t addr) {
    asm volatile("ldmatrix.sync.aligned.m8n8.x4.trans.shared.b16 {%0,%1,%2,%3}, [%4];"
        : "=r"(r[0]), "=r"(r[1]), "=r"(r[2]), "=r"(r[3]) : "r"(addr));
}
__device__ __forceinline__ void mma_bf16(float* c, const uint32_t* a, uint32_t b0, uint32_t b1) {
    asm volatile(
        "mma.sync.aligned.m16n8k16.row.col.f32.bf16.bf16.f32 "
        "{%0,%1,%2,%3}, {%4,%5,%6,%7}, {%8,%9}, {%0,%1,%2,%3};"
        : "+f"(c[0]), "+f"(c[1]), "+f"(c[2]), "+f"(c[3])
        : "r"(a[0]), "r"(a[1]), "r"(a[2]), "r"(a[3]), "r"(b0), "r"(b1));
}
__device__ __forceinline__ uint32_t pack_bf16(float a, float b) {
    __nv_bfloat162 t;
    t.x = __float2bfloat16(a); t.y = __float2bfloat16(b);
    return *(uint32_t*)&t;
}
__device__ __forceinline__ void split_store(bf16* ph, bf16* pl, size_t idx, float v0, float v1) {
    __nv_bfloat162 h, l;
    h.x = __float2bfloat16(v0); h.y = __float2bfloat16(v1);
    l.x = __float2bfloat16(v0 - __bfloat162float(h.x));
    l.y = __float2bfloat16(v1 - __bfloat162float(h.y));
    *(__nv_bfloat162*)&ph[idx] = h;
    *(__nv_bfloat162*)&pl[idx] = l;
}
__device__ __forceinline__ void cvt_split_u2(float4 b, uint2& hv, uint2& lv) {
    __nv_bfloat162 h0, h1, l0, l1;
    h0.x = __float2bfloat16(b.x); h0.y = __float2bfloat16(b.y);
    h1.x = __float2bfloat16(b.z); h1.y = __float2bfloat16(b.w);
    l0.x = __float2bfloat16(b.x - __bfloat162float(h0.x));
    l0.y = __float2bfloat16(b.y - __bfloat162float(h0.y));
    l1.x = __float2bfloat16(b.z - __bfloat162float(h1.x));
    l1.y = __float2bfloat16(b.w - __bfloat162float(h1.y));
    hv.x = *(uint32_t*)&h0; hv.y = *(uint32_t*)&h1;
    lv.x = *(uint32_t*)&l0; lv.y = *(uint32_t*)&l1;
}
#define CP_ASYNC16(sa, gp) \
    asm volatile("cp.async.cg.shared.global [%0], [%1], 16;" :: "r"(sa), "l"(gp))
#define CP_COMMIT() asm volatile("cp.async.commit_group;" ::: "memory")
#define CP_WAIT0() asm volatile("cp.async.wait_group 0;" ::: "memory")

// ---------------- transpose + bf16 split (V only) ----------------
__global__ __launch_bounds__(256) void transpose_split(const float* __restrict__ in,
                                                       bf16* __restrict__ oh,
                                                       bf16* __restrict__ ol,
                                                       int R, int C) {
    __shared__ float tile[32][33];
    int c0 = blockIdx.x * 32, r0 = blockIdx.y * 32;
    int tx = threadIdx.x & 31, ty = threadIdx.x >> 5;
    for (int i = ty; i < 32; i += 8)
        tile[i][tx] = in[(size_t)(r0 + i) * C + c0 + tx];
    __syncthreads();
    for (int i = ty; i < 32; i += 8) {
        float v = tile[tx][i];
        bf16 h = __float2bfloat16(v);
        oh[(size_t)(c0 + i) * R + r0 + tx] = h;
        ol[(size_t)(c0 + i) * R + r0 + tx] = __float2bfloat16(v - __bfloat162float(h));
    }
}

// ---------------- bf16x3 double-buffered tensor-core GEMM (R13 proven) ----------------
// mode 0: C=A@B   1: +res   4: A=compact g_hh rows, weighted scatter to g_ypart
#define STRIDE 40
#define BSTRIDE 136
#define ABUF 10240
#define BBUF 8704
#define GEMM_SMEM (4*ABUF + 4*BBUF)
__global__ __launch_bounds__(256, 1) void mma_gemm(const bf16* __restrict__ Ah_,
                                                   const bf16* __restrict__ Al_,
                                                   const float* __restrict__ B,
                                                   float* __restrict__ C,
                                                   const float* __restrict__ res,
                                                   int N, int K, int mode) {
    extern __shared__ char dyn[];
    uint32_t aAh = smem_u32(dyn);
    uint32_t aAl = aAh + 2 * ABUF;
    uint32_t aBh = aAh + 4 * ABUF;
    uint32_t aBl = aBh + 2 * BBUF;
    uint32_t* sAh32 = (uint32_t*)dyn;
    uint32_t* sAl32 = (uint32_t*)(dyn + 2 * ABUF);
    bf16* sBh = (bf16*)(dyn + 4 * ABUF);
    bf16* sBl = (bf16*)(dyn + 4 * ABUF + 2 * BBUF);
    __shared__ float swgt[128];
    __shared__ int sdst[128];

    int tid = threadIdx.x, wid = tid >> 5, lane = tid & 31;
    int e = blockIdx.z;
    int cnt = 0, goff = 0;
    int row0 = blockIdx.y * 128, col0 = blockIdx.x * 128;
    int K2 = K >> 1;
    const uint32_t* Ah = (const uint32_t*)Ah_;
    const uint32_t* Al = (const uint32_t*)Al_;
    if (mode == 4) {
        cnt = g_ecnt[e]; goff = g_eoff[e];
        if (row0 >= cnt) return;
        if (tid < 128) {
            int slot = row0 + tid;
            if (slot < cnt) {
                int p = g_elist[e * T + slot];
                int tt = p >> 1, ks = p & 1;
                swgt[tid] = g_gatew[tt * 2 + ks];
                sdst[tid] = tt * 2 + ks;
            } else { swgt[tid] = 0.f; sdst[tid] = -1; }
        }
        B += (size_t)e * (size_t)K * (size_t)N;
        __syncthreads();
    }

    int wr = wid & 3, wc = wid >> 2;
    float acc[2][8][4] = {};

    int nchunks = K >> 5;
    uint4 aRh4[2], aRl4[2];
    float4 bR[4];

    auto loadRegs = [&](int chunk) {
        int kc0 = chunk * 16;
        #pragma unroll
        for (int f = 0; f < 2; f++) {
            int fi = tid + f * 256; int r = fi >> 2, c4 = fi & 3;
            size_t arow = (mode == 4) ? (size_t)(goff + row0 + r) : (size_t)(row0 + r);
            aRh4[f] = *(const uint4*)&Ah[arow * K2 + kc0 + c4 * 4];
            aRl4[f] = *(const uint4*)&Al[arow * K2 + kc0 + c4 * 4];
        }
        int kr0 = chunk * 32;
        #pragma unroll
        for (int f = 0; f < 4; f++) {
            int fi = tid + f * 256; int r = fi >> 5, c = (fi & 31) * 4;
            bR[f] = *(const float4*)&B[(size_t)(kr0 + r) * N + col0 + c];
        }
    };
    auto storeRegs = [&](int buf) {
        int ao = buf * (ABUF / 4);
        #pragma unroll
        for (int f = 0; f < 2; f++) {
            int fi = tid + f * 256; int r = fi >> 2, c4 = fi & 3;
            int si = ao + r * (STRIDE / 2) + c4 * 4;
            *(uint4*)&sAh32[si] = aRh4[f];
            *(uint4*)&sAl32[si] = aRl4[f];
        }
        int bo = buf * (BBUF / 2);
        #pragma unroll
        for (int f = 0; f < 4; f++) {
            int fi = tid + f * 256; int r = fi >> 5, c = (fi & 31) * 4;
            int si = bo + r * BSTRIDE + c;
            uint2 hv, lv;
            cvt_split_u2(bR[f], hv, lv);
            *(uint2*)&sBh[si] = hv;
            *(uint2*)&sBl[si] = lv;
        }
    };

    int lrow = lane & 15;
    int lcol8 = (lane >> 4) << 3;
    int tb_k = (lane & 7) + ((lane >> 4) << 3);
    int tb_n = ((lane >> 3) & 1) << 3;

    loadRegs(0);
    storeRegs(0);
    __syncthreads();

    for (int i = 0; i < nchunks; i++) {
        int b = i & 1;
        if (i + 1 < nchunks) loadRegs(i + 1);
        uint32_t Aoff = (uint32_t)(b * ABUF);
        uint32_t Boff = (uint32_t)(b * BBUF);
        #pragma unroll
        for (int ks = 0; ks < 2; ks++) {
            int k0 = ks * 16;
            uint32_t ah[2][4], al[2][4];
            #pragma unroll
            for (int im = 0; im < 2; im++) {
                uint32_t off = (uint32_t)((wr * 32 + im * 16 + lrow) * STRIDE + k0 + lcol8) * 2 + Aoff;
                ldm_x4(ah[im], aAh + off);
                ldm_x4(al[im], aAl + off);
            }
            #pragma unroll
            for (int np = 0; np < 4; np++) {
                uint32_t off = (uint32_t)((k0 + tb_k) * BSTRIDE + wc * 64 + np * 16 + tb_n) * 2 + Boff;
                uint32_t bh[4], bl[4];
                ldm_x4_trans(bh, aBh + off);
                ldm_x4_trans(bl, aBl + off);
                #pragma unroll
                for (int im = 0; im < 2; im++) {
                    mma_bf16(acc[im][np * 2],     ah[im], bh[0], bh[2]);
                    mma_bf16(acc[im][np * 2],     ah[im], bl[0], bl[2]);
                    mma_bf16(acc[im][np * 2],     al[im], bh[0], bh[2]);
                    mma_bf16(acc[im][np * 2 + 1], ah[im], bh[1], bh[3]);
                    mma_bf16(acc[im][np * 2 + 1], ah[im], bl[1], bl[3]);
                    mma_bf16(acc[im][np * 2 + 1], al[im], bh[1], bh[3]);
                }
            }
        }
        if (i + 1 < nchunks) storeRegs(b ^ 1);
        __syncthreads();
    }

    // ---------------- epilogue ----------------
    #pragma unroll
    for (int im = 0; im < 2; im++) {
        #pragma unroll
        for (int nt = 0; nt < 8; nt++) {
            int col = wc * 64 + nt * 8 + (lane & 3) * 2;
            int n = col0 + col;
            #pragma unroll
            for (int half = 0; half < 2; half++) {
                int slot = wr * 32 + im * 16 + (lane >> 2) + half * 8;
                float v0 = acc[im][nt][half * 2], v1 = acc[im][nt][half * 2 + 1];
                if (mode == 0) {
                    *(float2*)&C[(size_t)(row0 + slot) * N + n] = make_float2(v0, v1);
                } else if (mode == 1) {
                    size_t di = (size_t)(row0 + slot) * N + n;
                    float2 rr = *(const float2*)&res[di];
                    *(float2*)&C[di] = make_float2(v0 + rr.x, v1 + rr.y);
                } else {
                    if (row0 + slot < cnt && sdst[slot] >= 0) {
                        float w = swgt[slot];
                        *(float2*)&g_ypart[(size_t)sdst[slot] * D + n] = make_float2(w * v0, w * v1);
                    }
                }
            }
        }
    }
}

// ---------------- fused MoE gate+up GEMM: h = silu(x@Wg) * (x@Wu) ----------------
#define BS2 72
#define GBUF 4608
#define GU_SMEM (4*ABUF + 8*GBUF)
__global__ __launch_bounds__(256, 1) void moe_gateup(const bf16* __restrict__ Ah_,
                                                     const bf16* __restrict__ Al_,
                                                     const float* __restrict__ Wg,
                                                     const float* __restrict__ Wu) {
    extern __shared__ char dyn[];
    uint32_t aAh = smem_u32(dyn);
    uint32_t aAl = aAh + 2 * ABUF;
    uint32_t aGh = aAh + 4 * ABUF;
    uint32_t aGl = aGh + 2 * GBUF;
    uint32_t aUh = aGh + 4 * GBUF;
    uint32_t aUl = aGh + 6 * GBUF;
    uint32_t* sAh32 = (uint32_t*)dyn;
    uint32_t* sAl32 = (uint32_t*)(dyn + 2 * ABUF);
    bf16* sGh = (bf16*)(dyn + 4 * ABUF);
    bf16* sGl = (bf16*)(dyn + 4 * ABUF + 2 * GBUF);
    bf16* sUh = (bf16*)(dyn + 4 * ABUF + 4 * GBUF);
    bf16* sUl = (bf16*)(dyn + 4 * ABUF + 6 * GBUF);
    __shared__ int toks[128];

    int tid = threadIdx.x, wid = tid >> 5, lane = tid & 31;
    int e = blockIdx.z;
    int cnt = g_ecnt[e], goff = g_eoff[e];
    int row0 = blockIdx.y * 128, col0 = blockIdx.x * 64;
    if (row0 >= cnt) return;
    Wg += (size_t)e * D * FF;
    Wu += (size_t)e * D * FF;
    if (tid < 128) {
        int slot = row0 + tid;
        toks[tid] = (slot < cnt) ? (g_elist[e * T + slot] >> 1) : 0;
    }
    __syncthreads();

    const uint32_t* Ah = (const uint32_t*)Ah_;
    const uint32_t* Al = (const uint32_t*)Al_;
    int wr = wid & 3, wc = wid >> 2;
    float aG[2][4][4] = {}, aU[2][4][4] = {};

    uint4 aRh4[2], aRl4[2];
    float4 gR[2], uR[2];
    auto loadRegs = [&](int chunk) {
        int kc0 = chunk * 16;
        #pragma unroll
        for (int f = 0; f < 2; f++) {
            int fi = tid + f * 256; int r = fi >> 2, c4 = fi & 3;
            size_t arow = (size_t)toks[r];
            aRh4[f] = *(const uint4*)&Ah[arow * (D / 2) + kc0 + c4 * 4];
            aRl4[f] = *(const uint4*)&Al[arow * (D / 2) + kc0 + c4 * 4];
        }
        int kr0 = chunk * 32;
        #pragma unroll
        for (int f = 0; f < 2; f++) {
            int fi = tid + f * 256; int r = fi >> 4, c = (fi & 15) * 4;
            gR[f] = *(const float4*)&Wg[(size_t)(kr0 + r) * FF + col0 + c];
            uR[f] = *(const float4*)&Wu[(size_t)(kr0 + r) * FF + col0 + c];
        }
    };
    auto storeRegs = [&](int buf) {
        int ao = buf * (ABUF / 4);
        #pragma unroll
        for (int f = 0; f < 2; f++) {
            int fi = tid + f * 256; int r = fi >> 2, c4 = fi & 3;
            int si = ao + r * (STRIDE / 2) + c4 * 4;
            *(uint4*)&sAh32[si] = aRh4[f];
            *(uint4*)&sAl32[si] = aRl4[f];
        }
        int bo = buf * (GBUF / 2);
        #pragma unroll
        for (int f = 0; f < 2; f++) {
            int fi = tid + f * 256; int r = fi >> 4, c = (fi & 15) * 4;
            int si = bo + r * BS2 + c;
            uint2 hv, lv;
            cvt_split_u2(gR[f], hv, lv);
            *(uint2*)&sGh[si] = hv; *(uint2*)&sGl[si] = lv;
            cvt_split_u2(uR[f], hv, lv);
            *(uint2*)&sUh[si] = hv; *(uint2*)&sUl[si] = lv;
        }
    };

    int lrow = lane & 15;
    int lcol8 = (lane >> 4) << 3;
    int tb_k = (lane & 7) + ((lane >> 4) << 3);
    int tb_n = ((lane >> 3) & 1) << 3;

    loadRegs(0);
    storeRegs(0);
    __syncthreads();

    int nchunks = D >> 5;
    for (int i = 0; i < nchunks; i++) {
        int b = i & 1;
        if (i + 1 < nchunks) loadRegs(i + 1);
        uint32_t Aoff = (uint32_t)(b * ABUF);
        uint32_t Boff = (uint32_t)(b * GBUF);
        #pragma unroll
        for (int ks = 0; ks < 2; ks++) {
            int k0 = ks * 16;
            uint32_t ah[2][4], al[2][4];
            #pragma unroll
            for (int im = 0; im < 2; im++) {
                uint32_t off = (uint32_t)((wr * 32 + im * 16 + lrow) * STRIDE + k0 + lcol8) * 2 + Aoff;
                ldm_x4(ah[im], aAh + off);
                ldm_x4(al[im], aAl + off);
            }
            #pragma unroll
            for (int np = 0; np < 2; np++) {
                uint32_t off = (uint32_t)((k0 + tb_k) * BS2 + wc * 32 + np * 16 + tb_n) * 2 + Boff;
                uint32_t bh[4], bl[4];
                ldm_x4_trans(bh, aGh + off);
                ldm_x4_trans(bl, aGl + off);
                #pragma unroll
                for (int im = 0; im < 2; im++) {
                    mma_bf16(aG[im][np * 2],     ah[im], bh[0], bh[2]);
                    mma_bf16(aG[im][np * 2],     ah[im], bl[0], bl[2]);
                    mma_bf16(aG[im][np * 2],     al[im], bh[0], bh[2]);
                    mma_bf16(aG[im][np * 2 + 1], ah[im], bh[1], bh[3]);
                    mma_bf16(aG[im][np * 2 + 1], ah[im], bl[1], bl[3]);
                    mma_bf16(aG[im][np * 2 + 1], al[im], bh[1], bh[3]);
                }
                ldm_x4_trans(bh, aUh + off);
                ldm_x4_trans(bl, aUl + off);
                #pragma unroll
                for (int im = 0; im < 2; im++) {
                    mma_bf16(aU[im][np * 2],     ah[im], bh[0], bh[2]);
                    mma_bf16(aU[im][np * 2],     ah[im], bl[0], bl[2]);
                    mma_bf16(aU[im][np * 2],     al[im], bh[0], bh[2]);
                    mma_bf16(aU[im][np * 2 + 1], ah[im], bh[1], bh[3]);
                    mma_bf16(aU[im][np * 2 + 1], ah[im], bl[1], bl[3]);
                    mma_bf16(aU[im][np * 2 + 1], al[im], bh[1], bh[3]);
                }
            }
        }
        if (i + 1 < nchunks) storeRegs(b ^ 1);
        __syncthreads();
    }

    #pragma unroll
    for (int im = 0; im < 2; im++) {
        #pragma unroll
        for (int nt = 0; nt < 4; nt++) {
            int n = col0 + wc * 32 + nt * 8 + (lane & 3) * 2;
            #pragma unroll
            for (int half = 0; half < 2; half++) {
                int slot = wr * 32 + im * 16 + (lane >> 2) + half * 8;
                if (row0 + slot < cnt) {
                    float gg0 = aG[im][nt][half * 2], gg1 = aG[im][nt][half * 2 + 1];
                    float u0 = aU[im][nt][half * 2], u1 = aU[im][nt][half * 2 + 1];
                    float h0 = u0 * (gg0 / (1.f + __expf(-gg0)));
                    float h1 = u1 * (gg1 / (1.f + __expf(-gg1)));
                    split_store(g_hh, g_hl, (size_t)(goff + row0 + slot) * FF + n, h0, h1);
                }
            }
        }
    }
}

// ---------------- LayerNorm (row cached in smem; bf16 hi/lo split out) ----------------
__global__ __launch_bounds__(256) void ln_kernel(const float* __restrict__ x,
                                                 const float* __restrict__ w,
                                                 const float* __restrict__ b,
                                                 float* __restrict__ out,
                                                 bf16* __restrict__ oh,
                                                 bf16* __restrict__ ol) {
    int t = blockIdx.x;
    const float* row = x + (size_t)t * D;
    __shared__ float srow[D];
    __shared__ float sh[256];
    int tid = threadIdx.x;
    float s = 0.f;
    for (int i = tid; i < D; i += 256) { float v = row[i]; srow[i] = v; s += v; }
    sh[tid] = s; __syncthreads();
    for (int o = 128; o; o >>= 1) { if (tid < o) sh[tid] += sh[tid + o]; __syncthreads(); }
    float mean = sh[0] / D;
    __syncthreads();
    float v = 0.f;
    for (int i = tid; i < D; i += 256) { float dd = srow[i] - mean; v += dd * dd; }
    sh[tid] = v; __syncthreads();
    for (int o = 128; o; o >>= 1) { if (tid < o) sh[tid] += sh[tid + o]; __syncthreads(); }
    float rstd = rsqrtf(sh[0] / D + 1e-5f);
    for (int i2 = tid; i2 < D / 2; i2 += 256) {
        int i = i2 * 2;
        float y0 = (srow[i] - mean) * rstd * w[i] + b[i];
        float y1 = (srow[i + 1] - mean) * rstd * w[i + 1] + b[i + 1];
        size_t di = (size_t)t * D + i;
        if (out) *(float2*)&out[di] = make_float2(y0, y1);
        split_store(oh, ol, di, y0, y1);
    }
}

// ---------------- RoPE + bf16 split of q, k ----------------
__global__ __launch_bounds__(256) void rope_split_kernel() {
    int t = blockIdx.x;
    for (int p = threadIdx.x; p < D / 2; p += 256) {
        int head = p >> 5;
        int i = p & 31;
        int i1 = t * D + head * HD + i;
        int i2 = i1 + 32;
        float inv = expf(-(2.0f * i / HD) * 9.210340371976184f);
        float fr = (float)t * inv;
        float c = cosf(fr), s = sinf(fr);
        float q1 = g_q[i1], q2 = g_q[i2];
        float k1 = g_k[i1], k2 = g_k[i2];
        float qa = q1 * c - q2 * s, qb = q2 * c + q1 * s;
        float ka = k1 * c - k2 * s, kb = k2 * c + k1 * s;
        bf16 h;
        h = __float2bfloat16(qa); g_qh[i1] = h; g_ql[i1] = __float2bfloat16(qa - __bfloat162float(h));
        h = __float2bfloat16(qb); g_qh[i2] = h; g_ql[i2] = __float2bfloat16(qb - __bfloat162float(h));
        h = __float2bfloat16(ka); g_kh[i1] = h; g_kl[i1] = __float2bfloat16(ka - __bfloat162float(h));
        h = __float2bfloat16(kb); g_kh[i2] = h; g_kl[i2] = __float2bfloat16(kb - __bfloat162float(h));
    }
}

// ---------------- tensor-core flash attention: cp.async double-buffered K/V ----------------
#define AS 72
#define ABUFSZ 36864
#define ATTN_SMEM (2 * ABUFSZ)
__global__ __launch_bounds__(128) void attn_mma_kernel() {
    extern __shared__ bf16 asm_[];
    int qt = blockIdx.x, h = blockIdx.y;
    int tid = threadIdx.x, w = tid >> 5, lane = tid & 31;
    int lrow = lane & 15, lcol8 = (lane >> 4) << 3;
    uint32_t aBase = smem_u32(asm_);
    uint32_t* sKBh32 = (uint32_t*)asm_;
    uint32_t* sKBl32 = (uint32_t*)((char*)asm_ + 9216);
    const uint32_t* qh32 = (const uint32_t*)g_qh;
    const uint32_t* ql32 = (const uint32_t*)g_ql;
    const uint32_t* kh32 = (const uint32_t*)g_kh;
    const uint32_t* kl32 = (const uint32_t*)g_kl;
    const uint32_t* vth32 = (const uint32_t*)g_vTh;
    const uint32_t* vtl32 = (const uint32_t*)g_vTl;

    // stage Q through buffer-0 K arrays, hoist Q fragments
    for (int i = tid; i < 64 * 32; i += 128) {
        int r = i >> 5, c = i & 31;
        sKBh32[r * (AS / 2) + c] = qh32[(size_t)(qt * 64 + r) * (D / 2) + h * 32 + c];
        sKBl32[r * (AS / 2) + c] = ql32[(size_t)(qt * 64 + r) * (D / 2) + h * 32 + c];
    }
    __syncthreads();
    uint32_t qah[4][4], qal[4][4];
    #pragma unroll
    for (int kc = 0; kc < 4; kc++) {
        uint32_t off = (uint32_t)((w * 16 + lrow) * AS + kc * 16 + lcol8) * 2;
        ldm_x4(qah[kc], aBase + off);
        ldm_x4(qal[kc], aBase + 9216 + off);
    }
    __syncthreads();

    auto issue_tile = [&](int kt, int b) {
        int kb = kt * 64;
        uint32_t base = aBase + (uint32_t)b * ABUFSZ;
        #pragma unroll
        for (int f = 0; f < 4; f++) {
            int j = tid + f * 128;
            int r = j >> 3, c4 = (j & 7) * 4;
            uint32_t so = (uint32_t)(r * (AS / 2) + c4) * 4;
            CP_ASYNC16(base + so,         kh32 + (size_t)(kb + r) * (D / 2) + h * 32 + c4);
            CP_ASYNC16(base + 9216 + so,  kl32 + (size_t)(kb + r) * (D / 2) + h * 32 + c4);
            CP_ASYNC16(base + 18432 + so, vth32 + (size_t)(h * 64 + r) * (T / 2) + (kb >> 1) + c4);
            CP_ASYNC16(base + 27648 + so, vtl32 + (size_t)(h * 64 + r) * (T / 2) + (kb >> 1) + c4);
        }
        CP_COMMIT();
    };

    float O[8][4] = {};
    float m_lo = -1e30f, m_hi = -1e30f, l_lo = 0.f, l_hi = 0.f;
    int row_lo = qt * 64 + w * 16 + (lane >> 2);
    int row_hi = row_lo + 8;
    int nkt = qt + 1;
    issue_tile(0, 0);
    for (int kt = 0; kt < nkt; kt++) {
        int b = kt & 1;
        CP_WAIT0();
        __syncthreads();
        if (kt + 1 < nkt) issue_tile(kt + 1, b ^ 1);
        uint32_t bb = aBase + (uint32_t)b * ABUFSZ;
        int kb = kt * 64;
        float S[8][4] = {};
        #pragma unroll
        for (int kc = 0; kc < 4; kc++) {
            #pragma unroll
            for (int jj = 0; jj < 4; jj++) {
                uint32_t off = (uint32_t)((jj * 16 + lrow) * AS + kc * 16 + lcol8) * 2;
                uint32_t bh[4], bl[4];
                ldm_x4(bh, bb + off);
                ldm_x4(bl, bb + 9216 + off);
                mma_bf16(S[2 * jj],     qah[kc], bh[0], bh[2]);
                mma_bf16(S[2 * jj],     qah[kc], bl[0], bl[2]);
                mma_bf16(S[2 * jj],     qal[kc], bh[0], bh[2]);
                mma_bf16(S[2 * jj + 1], qah[kc], bh[1], bh[3]);
                mma_bf16(S[2 * jj + 1], qah[kc], bl[1], bl[3]);
                mma_bf16(S[2 * jj + 1], qal[kc], bh[1], bh[3]);
            }
        }
        bool diag = (kt == qt);
        float mt_lo = -1e30f, mt_hi = -1e30f;
        #pragma unroll
        for (int j = 0; j < 8; j++) {
            int c0 = kb + j * 8 + ((lane & 3) << 1);
            float s0 = S[j][0] * 0.125f, s1 = S[j][1] * 0.125f;
            float s2 = S[j][2] * 0.125f, s3 = S[j][3] * 0.125f;
            if (diag) {
                if (c0 > row_lo) s0 = -1e30f;
                if (c0 + 1 > row_lo) s1 = -1e30f;
                if (c0 > row_hi) s2 = -1e30f;
                if (c0 + 1 > row_hi) s3 = -1e30f;
            }
            S[j][0] = s0; S[j][1] = s1; S[j][2] = s2; S[j][3] = s3;
            mt_lo = fmaxf(mt_lo, fmaxf(s0, s1));
            mt_hi = fmaxf(mt_hi, fmaxf(s2, s3));
        }
        mt_lo = fmaxf(mt_lo, __shfl_xor_sync(0xffffffff, mt_lo, 1));
        mt_lo = fmaxf(mt_lo, __shfl_xor_sync(0xffffffff, mt_lo, 2));
        mt_hi = fmaxf(mt_hi, __shfl_xor_sync(0xffffffff, mt_hi, 1));
        mt_hi = fmaxf(mt_hi, __shfl_xor_sync(0xffffffff, mt_hi, 2));
        float mn_lo = fmaxf(m_lo, mt_lo), mn_hi = fmaxf(m_hi, mt_hi);
        float co_lo = __expf(m_lo - mn_lo), co_hi = __expf(m_hi - mn_hi);
        l_lo *= co_lo; l_hi *= co_hi;
        #pragma unroll
        for (int j = 0; j < 8; j++) {
            O[j][0] *= co_lo; O[j][1] *= co_lo;
            O[j][2] *= co_hi; O[j][3] *= co_hi;
            S[j][0] = __expf(S[j][0] - mn_lo);
            S[j][1] = __expf(S[j][1] - mn_lo);
            S[j][2] = __expf(S[j][2] - mn_hi);
            S[j][3] = __expf(S[j][3] - mn_hi);
            l_lo += S[j][0] + S[j][1];
            l_hi += S[j][2] + S[j][3];
        }
        m_lo = mn_lo; m_hi = mn_hi;
        #pragma unroll
        for (int kc = 0; kc < 4; kc++) {
            uint32_t pah[4], pal[4];
            {
                float p0 = S[2 * kc][0], p1 = S[2 * kc][1], p2 = S[2 * kc][2], p3 = S[2 * kc][3];
                float q0 = S[2 * kc + 1][0], q1 = S[2 * kc + 1][1], q2 = S[2 * kc + 1][2], q3 = S[2 * kc + 1][3];
                pah[0] = pack_bf16(p0, p1); pah[1] = pack_bf16(p2, p3);
                pah[2] = pack_bf16(q0, q1); pah[3] = pack_bf16(q2, q3);
                __nv_bfloat162 t;
                t = *(__nv_bfloat162*)&pah[0];
                pal[0] = pack_bf16(p0 - __bfloat162float(t.x), p1 - __bfloat162float(t.y));
                t = *(__nv_bfloat162*)&pah[1];
                pal[1] = pack_bf16(p2 - __bfloat162float(t.x), p3 - __bfloat162float(t.y));
                t = *(__nv_bfloat162*)&pah[2];
                pal[2] = pack_bf16(q0 - __bfloat162float(t.x), q1 - __bfloat162float(t.y));
                t = *(__nv_bfloat162*)&pah[3];
                pal[3] = pack_bf16(q2 - __bfloat162float(t.x), q3 - __bfloat162float(t.y));
            }
            #pragma unroll
            for (int dd = 0; dd < 4; dd++) {
                uint32_t off = (uint32_t)((dd * 16 + lrow) * AS + kc * 16 + lcol8) * 2;
                uint32_t vh[4], vl[4];
                ldm_x4(vh, bb + 18432 + off);
                ldm_x4(vl, bb + 27648 + off);
                mma_bf16(O[2 * dd],     pah, vh[0], vh[2]);
                mma_bf16(O[2 * dd],     pah, vl[0], vl[2]);
                mma_bf16(O[2 * dd],     pal, vh[0], vh[2]);
                mma_bf16(O[2 * dd + 1], pah, vh[1], vh[3]);
                mma_bf16(O[2 * dd + 1], pah, vl[1], vl[3]);
                mma_bf16(O[2 * dd + 1], pal, vh[1], vh[3]);
            }
        }
    }
    l_lo += __shfl_xor_sync(0xffffffff, l_lo, 1);
    l_lo += __shfl_xor_sync(0xffffffff, l_lo, 2);
    l_hi += __shfl_xor_sync(0xffffffff, l_hi, 1);
    l_hi += __shfl_xor_sync(0xffffffff, l_hi, 2);
    float inv_lo = 1.f / l_lo, inv_hi = 1.f / l_hi;
    #pragma unroll
    for (int j = 0; j < 8; j++) {
        int col = h * 64 + j * 8 + ((lane & 3) << 1);
        split_store(g_attnh, g_attnl, (size_t)row_lo * D + col, O[j][0] * inv_lo, O[j][1] * inv_lo);
        split_store(g_attnh, g_attnl, (size_t)row_hi * D + col, O[j][2] * inv_hi, O[j][3] * inv_hi);
    }
}

// ---------------- router ----------------
__global__ __launch_bounds__(256) void zero_cnt_kernel() {
    if (threadIdx.x < NE) g_ecnt[threadIdx.x] = 0;
}

__global__ __launch_bounds__(256) void router_kernel(const float* __restrict__ wr) {
    int t = blockIdx.x;
    int tid = threadIdx.x, lane = tid & 31, w = tid >> 5;
    const float* x = g_xln2 + (size_t)t * D;
    float s = 0.f;
    for (int d = lane; d < D; d += 32) s += x[d] * wr[d * NE + w];
    #pragma unroll
    for (int o = 16; o; o >>= 1) s += __shfl_xor_sync(0xffffffff, s, o);
    __shared__ float lg[NE];
    if (lane == 0) lg[w] = s;
    __syncthreads();
    if (tid == 0) {
        float mx = -1e30f;
        #pragma unroll
        for (int e = 0; e < NE; e++) mx = fmaxf(mx, lg[e]);
        float ex[NE], sum = 0.f;
        #pragma unroll
        for (int e = 0; e < NE; e++) { ex[e] = expf(lg[e] - mx); sum += ex[e]; }
        g_lse[t] = mx + logf(sum);
        float pr[NE];
        #pragma unroll
        for (int e = 0; e < NE; e++) { pr[e] = ex[e] / sum; g_probs[t * NE + e] = pr[e]; }
        int e0 = 0; float b0 = pr[0];
        #pragma unroll
        for (int e = 1; e < NE; e++) if (pr[e] > b0) { b0 = pr[e]; e0 = e; }
        int e1 = -1; float b1 = -1.f;
        #pragma unroll
        for (int e = 0; e < NE; e++) if (e != e0 && pr[e] > b1) { b1 = pr[e]; e1 = e; }
        float ws = b0 + b1;
        g_gatew[t * 2 + 0] = b0 / ws;
        g_gatew[t * 2 + 1] = b1 / ws;
        g_topk[t * 2 + 0] = e0;
        g_topk[t * 2 + 1] = e1;
        int s0 = atomicAdd(&g_ecnt[e0], 1); g_elist[e0 * T + s0] = (t << 1) | 0;
        int s1 = atomicAdd(&g_ecnt[e1], 1); g_elist[e1 * T + s1] = (t << 1) | 1;
    }
}

__global__ void scan_kernel() {
    if (threadIdx.x == 0) {
        int o = 0;
        for (int e = 0; e < NE; e++) { g_eoff[e] = o; o += g_ecnt[e]; }
    }
}

// ---------------- final combine (float4) ----------------
__global__ __launch_bounds__(256) void combine_kernel(float* __restrict__ out) {
    int i4 = (blockIdx.x * 256 + threadIdx.x) * 4;
    int t = i4 >> 10, d = i4 & 1023;
    float4 a = *(const float4*)&g_hs1[i4];
    float4 b = *(const float4*)&g_ypart[(size_t)(t * 2) * D + d];
    float4 c = *(const float4*)&g_ypart[(size_t)(t * 2 + 1) * D + d];
    *(float4*)&out[i4] = make_float4(a.x + b.x + c.x, a.y + b.y + c.y,
                                     a.z + b.z + c.z, a.w + b.w + c.w);
}

// ---------------- aux losses ----------------
__global__ __launch_bounds__(256) void aux_kernel(float* __restrict__ out) {
    __shared__ float sh[256];
    __shared__ float totps[NE];
    __shared__ int totcnt[NE];
    __shared__ float zsave;
    int tid = threadIdx.x;
    if (tid < NE) totcnt[tid] = 0;
    float z = 0.f, ps[NE]; int cnt[NE];
    #pragma unroll
    for (int e = 0; e < NE; e++) { ps[e] = 0.f; cnt[e] = 0; }
    for (int t = tid; t < T; t += 256) {
        float l = g_lse[t]; z += l * l;
        #pragma unroll
        for (int e = 0; e < NE; e++) ps[e] += g_probs[t * NE + e];
        cnt[g_topk[t * 2]]++; cnt[g_topk[t * 2 + 1]]++;
    }
    sh[tid] = z; __syncthreads();
    for (int o = 128; o; o >>= 1) { if (tid < o) sh[tid] += sh[tid + o]; __syncthreads(); }
    if (tid == 0) zsave = sh[0];
    __syncthreads();
    for (int e = 0; e < NE; e++) {
        sh[tid] = ps[e]; __syncthreads();
        for (int o = 128; o; o >>= 1) { if (tid < o) sh[tid] += sh[tid + o]; __syncthreads(); }
        if (tid == 0) totps[e] = sh[0];
        __syncthreads();
        atomicAdd(&totcnt[e], cnt[e]);
    }
    __syncthreads();
    if (tid == 0) {
        float zl = 0.001f * zsave / T;
        float lb = 0.f;
        for (int e = 0; e < NE; e++) lb += ((float)totcnt[e] / T) * (totps[e] / T);
        out[T * D] = zl + 0.01f * lb;
    }
}

// ---------------- launch ----------------
extern "C" void kernel_launch(void* const* d_in, const int* in_sizes, int n_in,
                              void* d_out, int out_size) {
    const float* hs  = (const float*)d_in[0];
    const float* l1w = (const float*)d_in[3];
    const float* l1b = (const float*)d_in[4];
    const float* l2w = (const float*)d_in[5];
    const float* l2b = (const float*)d_in[6];
    const float* wq  = (const float*)d_in[7];
    const float* wk  = (const float*)d_in[8];
    const float* wv  = (const float*)d_in[9];
    const float* wo  = (const float*)d_in[10];
    const float* wr  = (const float*)d_in[11];
    const float* wg  = (const float*)d_in[12];
    const float* wu  = (const float*)d_in[13];
    const float* wd  = (const float*)d_in[14];
    float* out = (float*)d_out;

    float *q, *k, *v, *hs1, *xln2;
    bf16 *xlnh, *xlnl, *xln2h, *xln2l, *attnh, *attnl, *hh, *hl, *vTh, *vTl;
    cudaGetSymbolAddress((void**)&q,     g_q);
    cudaGetSymbolAddress((void**)&k,     g_k);
    cudaGetSymbolAddress((void**)&v,     g_v);
    cudaGetSymbolAddress((void**)&hs1,   g_hs1);
    cudaGetSymbolAddress((void**)&xln2,  g_xln2);
    cudaGetSymbolAddress((void**)&xlnh,  g_xlnh);
    cudaGetSymbolAddress((void**)&xlnl,  g_xlnl);
    cudaGetSymbolAddress((void**)&xln2h, g_xln2h);
    cudaGetSymbolAddress((void**)&xln2l, g_xln2l);
    cudaGetSymbolAddress((void**)&attnh, g_attnh);
    cudaGetSymbolAddress((void**)&attnl, g_attnl);
    cudaGetSymbolAddress((void**)&hh,    g_hh);
    cudaGetSymbolAddress((void**)&hl,    g_hl);
    cudaGetSymbolAddress((void**)&vTh,   g_vTh);
    cudaGetSymbolAddress((void**)&vTl,   g_vTl);

    cudaFuncSetAttribute(attn_mma_kernel, cudaFuncAttributeMaxDynamicSharedMemorySize, ATTN_SMEM);
    cudaFuncSetAttribute(mma_gemm, cudaFuncAttributeMaxDynamicSharedMemorySize, GEMM_SMEM);
    cudaFuncSetAttribute(moe_gateup, cudaFuncAttributeMaxDynamicSharedMemorySize, GU_SMEM);

    ln_kernel<<<T, 256>>>(hs, l1w, l1b, nullptr, xlnh, xlnl);
    dim3 gproj(D / 128, T / 128, 1);
    mma_gemm<<<gproj, 256, GEMM_SMEM>>>(xlnh, xlnl, wq, q, nullptr, D, D, 0);
    mma_gemm<<<gproj, 256, GEMM_SMEM>>>(xlnh, xlnl, wk, k, nullptr, D, D, 0);
    mma_gemm<<<gproj, 256, GEMM_SMEM>>>(xlnh, xlnl, wv, v, nullptr, D, D, 0);
    rope_split_kernel<<<T, 256>>>();
    transpose_split<<<dim3(D / 32, T / 32, 1), 256>>>(v, vTh, vTl, T, D);
    attn_mma_kernel<<<dim3(T / 64, NH), 128, ATTN_SMEM>>>();
    mma_gemm<<<gproj, 256, GEMM_SMEM>>>(attnh, attnl, wo, hs1, hs, D, D, 1);
    ln_kernel<<<T, 256>>>(hs1, l2w, l2b, xln2, xln2h, xln2l);
    zero_cnt_kernel<<<1, 256>>>();
    router_kernel<<<T, 256>>>(wr);
    scan_kernel<<<1, 32>>>();
    moe_gateup<<<dim3(FF / 64, T / 128, NE), 256, GU_SMEM>>>(xln2h, xln2l, wg, wu);
    dim3 gdown(D / 128, T / 128, NE);
    mma_gemm<<<gdown, 256, GEMM_SMEM>>>(hh, hl, wd, nullptr, nullptr, D, FF, 4);
    combine_kernel<<<(T * D) / 1024, 256>>>(out);
    if (out_size > T * D) aux_kernel<<<1, 256>>>(out);
}